// round 14
// baseline (speedup 1.0000x reference)
#include <cuda_runtime.h>
#include <math.h>

#define BB 32
#define SS 32
#define TT 31
#define HH 256
#define H3 768
#define VV 12000
#define NTOK 32
#define BOUND 16
#define ATP 1024
#define NPAIR 16
#define CL 4
#define NMAIN (NPAIR * CL)
#define GBM 128
#define GBN 128
#define GBK 16
#define NCB ((VV + GBN - 1) / GBN)
#define NTB 8

// ---------------- metadata ----------------
__device__ signed char g_la[TT][BB];
__device__ signed char g_npop[TT][BB];
__device__ signed char g_pop_slot[TT][BB][SS];
__device__ signed char g_pop_tok[TT][BB][SS];
__device__ signed char g_spush_slot[TT][BB];
__device__ signed char g_spush_tok[TT][BB];
__device__ signed char g_bpush_tok[TT][BB];
__device__ signed char g_stop[TT][BB];

__device__ __align__(16) float g_tokxw[4][NTOK][H3];
__device__ __align__(16) float g_attT[HH][ATP];   // row = t*BB + b
__device__ unsigned long long g_amax[BB * TT];
__device__ int g_tdone[TT];
__device__ int g_gdone;

// ---------------- asm helpers ----------------
__device__ __forceinline__ unsigned long long pk2(float lo, float hi) {
    unsigned long long r;
    asm("mov.b64 %0, {%1, %2};" : "=l"(r) : "f"(lo), "f"(hi));
    return r;
}
__device__ __forceinline__ void upk2(float& lo, float& hi, unsigned long long v) {
    asm("mov.b64 {%0, %1}, %2;" : "=f"(lo), "=f"(hi) : "l"(v));
}
__device__ __forceinline__ void ffma2(unsigned long long& d, unsigned long long a,
                                      unsigned long long b) {
    asm("fma.rn.f32x2 %0, %1, %2, %3;" : "=l"(d) : "l"(a), "l"(b), "l"(d));
}
__device__ __forceinline__ unsigned smem_u32(const void* p) {
    return (unsigned)__cvta_generic_to_shared(p);
}
__device__ __forceinline__ void st_peer(unsigned addr, unsigned peer, float v) {
    unsigned pa;
    asm volatile("mapa.shared::cluster.u32 %0, %1, %2;" : "=r"(pa) : "r"(addr), "r"(peer));
    asm volatile("st.shared::cluster.f32 [%0], %1;" :: "r"(pa), "f"(v) : "memory");
}
__device__ __forceinline__ void st_peer3(unsigned addr, int rank, float v) {
    st_peer(addr, (unsigned)((rank + 1) & 3), v);
    st_peer(addr, (unsigned)((rank + 2) & 3), v);
    st_peer(addr, (unsigned)((rank + 3) & 3), v);
}
#define CLUSTER_SYNC() do { \
    asm volatile("barrier.cluster.arrive.aligned;" ::: "memory"); \
    asm volatile("barrier.cluster.wait.aligned;" ::: "memory"); } while (0)

#define CP16(dst, src) \
    asm volatile("cp.async.cg.shared.global [%0], [%1], 16;" :: "r"(dst), "l"(src))
#define CP_COMMIT() asm volatile("cp.async.commit_group;" ::: "memory")

__device__ __forceinline__ float sigm(float v) { return 1.f / (1.f + expf(-v)); }
__device__ __forceinline__ void fma4(float4& a, float x, float4 m) {
    a.x += x * m.x; a.y += x * m.y; a.z += x * m.z; a.w += x * m.w;
}

// ---------------- prep kernel: control (block 0) + tokxw (blocks 1..128) ------
__global__ void prep_kernel(const int* __restrict__ actions,
                            const float* __restrict__ embed,
                            const float* __restrict__ aW, const float* __restrict__ ab,
                            const float* __restrict__ bW, const float* __restrict__ bb,
                            const float* __restrict__ sW, const float* __restrict__ sb,
                            const float* __restrict__ rW, const float* __restrict__ rb) {
    if (blockIdx.x == 0) {
        if (threadIdx.x >= 32) return;
        int b = threadIdx.x;
        for (int r = b; r < BB * TT; r += 32) g_amax[r] = 0ull;
        if (b < TT) g_tdone[b] = 0;
        if (b == 0) g_gdone = 0;
        int st = -1, tt_ = -1, bt = 0, acc = 1;
        signed char tm[SS];
        signed char stok[SS];

        for (int t = 0; t < TT; t++) {
            int a = actions[b * SS + t];
            int la = a * acc;
            int is_red = (la == 2) ? 1 : 0;
            int is_nt  = (la > 2 && la < BOUND) ? 1 : 0;
            int is_gen = (la >= BOUND) ? 1 : 0;

            int np = 0;
            int ir = is_red, aok = 1;
            for (int i = 0; i < SS; i++) {
                if (!(ir && aok)) break;
                int can1 = (st >= 0);
                int pslot = -1;
                if (can1) { pslot = st; st--; }
                aok = aok & can1;
                int tag = 0;
                if (ir && aok) {
                    int can2 = (tt_ >= 0);
                    if (can2) { tag = tm[tt_]; tt_--; }
                    aok = aok & can2;
                }
                int outm = ir & aok;
                if (outm) {
                    g_pop_slot[t][b][np] = (signed char)pslot;
                    g_pop_tok[t][b][np]  = stok[pslot];
                    np++;
                }
                ir = (ir - tag) * aok;
            }
            int racc = aok;
            int sslot = -1, stokv = -2;
            if (is_red && racc) {
                int can = (st + 1 < SS);
                if (can) { st++; sslot = st; stokv = -1; stok[st] = -1; }
                racc &= can;
                if (racc) {
                    int can2 = (tt_ + 1 < SS);
                    if (can2) { tt_++; tm[tt_] = 0; }
                    racc &= can2;
                }
            }
            unsigned ball = __ballot_sync(0xffffffffu, is_red);
            int tot = np;
            for (int o = 16; o > 0; o >>= 1) tot += __shfl_xor_sync(0xffffffffu, tot, o);
            int red_mult = 1;
            if (ball) red_mult = (tot == 0) ? 0 : racc;
            acc *= red_mult;

            if (is_nt) {
                int s5 = (st + 1 < SS);
                if (s5) { st++; stok[st] = (signed char)la; sslot = st; stokv = la; }
                acc *= s5;
                if (s5) {
                    int s6 = (tt_ + 1 < SS);
                    if (s6) { tt_++; tm[tt_] = 1; }
                    acc *= s6;
                }
            }
            int bpush = -1;
            if (is_gen) {
                int s7 = (st + 1 < SS);
                if (s7) { st++; stok[st] = (signed char)la; sslot = st; stokv = la; }
                acc *= s7;
                int s8 = 1;
                if (s7) {
                    s8 = (tt_ + 1 < SS);
                    if (s8) { tt_++; tm[tt_] = 0; }
                    acc *= s8;
                }
                if (s7 && s8) {
                    int s9 = (bt + 1 < SS);
                    if (s9) { bt++; bpush = la; }
                    acc *= s9;
                }
            }
            g_bpush_tok[t][b]  = (signed char)bpush;
            g_la[t][b]         = (signed char)la;
            g_npop[t][b]       = (signed char)np;
            g_spush_slot[t][b] = (signed char)sslot;
            g_spush_tok[t][b]  = (signed char)stokv;
            g_stop[t][b]       = (signed char)st;
        }
        return;
    }

    int bx = blockIdx.x - 1;   // 0..127
    int tok = bx & 31;
    int set = bx >> 5;
    const float* W  = (set == 0) ? aW : (set == 1) ? bW : (set == 2) ? sW : rW;
    const float* bi = (set == 0) ? ab : (set == 1) ? bb : (set == 2) ? sb : rb;
    int tid = threadIdx.x;  // 192 threads
    const float4* W4 = (const float4*)W;
    float4 acc = __ldg((const float4*)bi + tid);
    const float* x = embed + (size_t)tok * HH;
#pragma unroll 8
    for (int k = 0; k < HH; k++) {
        float xk = __ldg(x + k);
        float4 w = __ldg(W4 + k * 192 + tid);
        acc.x += xk * w.x; acc.y += xk * w.y; acc.z += xk * w.z; acc.w += xk * w.w;
    }
    ((float4*)(&g_tokxw[set][tok][0]))[tid] = acc;
}

// ---------------- quarter matvec for a lane pair (single matrix) ----------------
__device__ __forceinline__ void mvq_pair(const float* __restrict__ M,
                                         const float* __restrict__ x0,
                                         const float* __restrict__ x1,
                                         float* out0, float* out1,
                                         const float* __restrict__ bias,
                                         int tid, int rank,
                                         float* part0, float* part1) {
    __syncthreads();
    int w = tid >> 5, l = tid & 31;
    const float* xs0 = x0 + w * 32;
    const float* xs1 = x1 + w * 32;
    const float4* Mrow = (const float4*)M + (size_t)(w * 32) * 192;
    int col0 = (l >> 4) * 64 + rank * 16 + (l & 15);
    int col1 = 128 + rank * 16 + l;
    float4 a0 = make_float4(0.f, 0.f, 0.f, 0.f), b0 = a0, a1 = a0, b1 = a0;
#pragma unroll 4
    for (int k = 0; k < 32; k++) {
        float x0k = xs0[k], x1k = xs1[k];
        float4 m0 = __ldg(Mrow + k * 192 + col0);
        fma4(a0, x0k, m0); fma4(b0, x1k, m0);
        if (l < 16) {
            float4 m1 = __ldg(Mrow + k * 192 + col1);
            fma4(a1, x0k, m1); fma4(b1, x1k, m1);
        }
    }
    float4* p40 = (float4*)part0 + w * 48;
    float4* p41 = (float4*)part1 + w * 48;
    p40[l] = a0; p41[l] = b0;
    if (l < 16) { p40[32 + l] = a1; p41[32 + l] = b1; }
    __syncthreads();
    if (tid < 192) {
        float s0 = 0.f, s1 = 0.f;
#pragma unroll
        for (int w2 = 0; w2 < 8; w2++) { s0 += part0[w2 * 192 + tid]; s1 += part1[w2 * 192 + tid]; }
        int f4i = tid >> 2;
        int g = f4i >> 4, o = f4i & 15;
        int gc = g * 256 + rank * 64 + o * 4 + (tid & 3);
        if (bias) { float bv = __ldg(bias + gc); s0 += bv; s1 += bv; }
        out0[gc] = s0; out1[gc] = s1;
    }
}

// ---------------- generic dual matvec (two matrices, two x-streams each) --------
__device__ __forceinline__ void mvq2g_pair(
    const float* __restrict__ M1,
    const float* __restrict__ x1_0, const float* __restrict__ x1_1,
    float* o1_0, float* o1_1,
    const float* __restrict__ M2,
    const float* __restrict__ x2_0, const float* __restrict__ x2_1,
    float* o2_0, float* o2_1,
    int tid, int rank, float* part) {
    __syncthreads();
    int w = tid >> 5, l = tid & 31;
    bool lo = (l < 16);
    int col0 = (l >> 4) * 64 + rank * 16 + (l & 15);
    int col1 = 128 + rank * 16 + l;
    const float4* M1R = (const float4*)M1 + (size_t)(w * 32) * 192;
    const float4* M2R = (const float4*)M2 + (size_t)(w * 32) * 192;
    const float* a0s = x1_0 + w * 32;
    const float* a1s = x1_1 + w * 32;
    const float* b0s = x2_0 + w * 32;
    const float* b1s = x2_1 + w * 32;
    float4 z = make_float4(0.f, 0.f, 0.f, 0.f);
    float4 pA0 = z, pB0 = z, pA1 = z, pB1 = z;
    float4 qA0 = z, qB0 = z, qA1 = z, qB1 = z;
#pragma unroll 2
    for (int k = 0; k < 32; k++) {
        float xa0 = a0s[k], xa1 = a1s[k];
        float4 m1 = __ldg(M1R + k * 192 + col0);
        fma4(pA0, xa0, m1); fma4(pB0, xa1, m1);
        float xb0 = b0s[k], xb1 = b1s[k];
        float4 m2 = __ldg(M2R + k * 192 + col0);
        fma4(qA0, xb0, m2); fma4(qB0, xb1, m2);
        if (lo) {
            float4 m1b = __ldg(M1R + k * 192 + col1);
            fma4(pA1, xa0, m1b); fma4(pB1, xa1, m1b);
            float4 m2b = __ldg(M2R + k * 192 + col1);
            fma4(qA1, xb0, m2b); fma4(qB1, xb1, m2b);
        }
    }
    float4* p0 = (float4*)(part + 0 * 1536) + w * 48;
    float4* p1 = (float4*)(part + 1 * 1536) + w * 48;
    float4* p2 = (float4*)(part + 2 * 1536) + w * 48;
    float4* p3 = (float4*)(part + 3 * 1536) + w * 48;
    p0[l] = pA0; p1[l] = pB0; p2[l] = qA0; p3[l] = qB0;
    if (lo) { p0[32 + l] = pA1; p1[32 + l] = pB1; p2[32 + l] = qA1; p3[32 + l] = qB1; }
    __syncthreads();
    if (tid < 192) {
        int f4i = tid >> 2;
        int g = f4i >> 4, o = f4i & 15;
        int gc = g * 256 + rank * 64 + o * 4 + (tid & 3);
        float s0 = 0.f, s1 = 0.f, r0 = 0.f, r1 = 0.f;
#pragma unroll
        for (int w2 = 0; w2 < 8; w2++) {
            s0 += part[0 * 1536 + w2 * 192 + tid];
            s1 += part[1 * 1536 + w2 * 192 + tid];
            r0 += part[2 * 1536 + w2 * 192 + tid];
            r1 += part[3 * 1536 + w2 * 192 + tid];
        }
        o1_0[gc] = s0; o1_1[gc] = s1;
        o2_0[gc] = r0; o2_1[gc] = r1;
    }
}

// ---------------- dual matvec (sW and rW over SAME x); rW quarter cached --------
__device__ __forceinline__ void mvq2sr_pair(
    const float* __restrict__ Ms, const float* __restrict__ Mr,
    const float* __restrict__ x0, const float* __restrict__ x1,
    float* outS0, float* outS1,
    float* cR0, float* cR1, bool wr0, bool wr1,
    const float* __restrict__ sbias, const float* __restrict__ rbias,
    int tid, int rank, float* part) {
    __syncthreads();
    int w = tid >> 5, l = tid & 31;
    bool lo = (l < 16);
    int col0 = (l >> 4) * 64 + rank * 16 + (l & 15);
    int col1 = 128 + rank * 16 + l;
    const float4* MsR = (const float4*)Ms + (size_t)(w * 32) * 192;
    const float4* MrR = (const float4*)Mr + (size_t)(w * 32) * 192;
    const float* xs0 = x0 + w * 32;
    const float* xs1 = x1 + w * 32;
    float4 z = make_float4(0.f, 0.f, 0.f, 0.f);
    float4 sA0 = z, sB0 = z, sA1 = z, sB1 = z;
    float4 rA0 = z, rB0 = z, rA1 = z, rB1 = z;
#pragma unroll 2
    for (int k = 0; k < 32; k++) {
        float x0k = xs0[k], x1k = xs1[k];
        float4 ms = __ldg(MsR + k * 192 + col0);
        fma4(sA0, x0k, ms); fma4(sB0, x1k, ms);
        float4 mr = __ldg(MrR + k * 192 + col0);
        fma4(rA0, x0k, mr); fma4(rB0, x1k, mr);
        if (lo) {
            float4 ms1 = __ldg(MsR + k * 192 + col1);
            fma4(sA1, x0k, ms1); fma4(sB1, x1k, ms1);
            float4 mr1 = __ldg(MrR + k * 192 + col1);
            fma4(rA1, x0k, mr1); fma4(rB1, x1k, mr1);
        }
    }
    float4* p0 = (float4*)(part + 0 * 1536) + w * 48;
    float4* p1 = (float4*)(part + 1 * 1536) + w * 48;
    float4* p2 = (float4*)(part + 2 * 1536) + w * 48;
    float4* p3 = (float4*)(part + 3 * 1536) + w * 48;
    p0[l] = sA0; p1[l] = sB0; p2[l] = rA0; p3[l] = rB0;
    if (lo) { p0[32 + l] = sA1; p1[32 + l] = sB1; p2[32 + l] = rA1; p3[32 + l] = rB1; }
    __syncthreads();
    if (tid < 192) {
        int f4i = tid >> 2;
        int g = f4i >> 4, o = f4i & 15;
        int gc = g * 256 + rank * 64 + o * 4 + (tid & 3);
        float s0 = 0.f, s1 = 0.f, r0 = 0.f, r1 = 0.f;
#pragma unroll
        for (int w2 = 0; w2 < 8; w2++) {
            s0 += part[0 * 1536 + w2 * 192 + tid];
            s1 += part[1 * 1536 + w2 * 192 + tid];
            r0 += part[2 * 1536 + w2 * 192 + tid];
            r1 += part[3 * 1536 + w2 * 192 + tid];
        }
        float sbv = __ldg(sbias + gc), rbv = __ldg(rbias + gc);
        outS0[gc] = s0 + sbv; outS1[gc] = s1 + sbv;
        int ci = g * 64 + o * 4 + (tid & 3);
        if (wr0) cR0[ci] = r0 + rbv;
        if (wr1) cR1[ci] = r1 + rbv;
    }
}

// ---------------- single attention piece (lane pair), low lanes only ------------
__device__ __forceinline__ void pieceq_pair(const float* __restrict__ Wp,
                                            const float* __restrict__ x0,
                                            const float* __restrict__ x1,
                                            float* out0, float* out1,
                                            bool act0, bool act1,
                                            int tid, int rank,
                                            float* part0, float* part1) {
    __syncthreads();
    int w = tid >> 5, l = tid & 31;
    if (l < 16) {
        const float* xs0 = x0 + w * 32;
        const float* xs1 = x1 + w * 32;
        const float4* W4 = (const float4*)Wp + (size_t)(w * 32) * 64 + rank * 16 + l;
        float4 a = make_float4(0.f, 0.f, 0.f, 0.f), b = a;
#pragma unroll 4
        for (int k = 0; k < 32; k++) {
            float4 m = __ldg(W4 + k * 64);
            float x0k = xs0[k], x1k = xs1[k];
            fma4(a, x0k, m); fma4(b, x1k, m);
        }
        ((float4*)part0)[w * 16 + l] = a;
        ((float4*)part1)[w * 16 + l] = b;
    }
    __syncthreads();
    if (tid < 64) {
        float s0 = 0.f, s1 = 0.f;
#pragma unroll
        for (int w2 = 0; w2 < 8; w2++) { s0 += part0[w2 * 64 + tid]; s1 += part1[w2 * 64 + tid]; }
        if (act0) out0[tid] = s0;
        if (act1) out1[tid] = s1;
    }
}

// ---------------- dual attention pieces: low lanes X, high lanes Y --------------
__device__ __forceinline__ void piece2_pair(
    const float* __restrict__ WX,
    const float* __restrict__ xX0, const float* __restrict__ xX1,
    float* oX0, float* oX1, bool aX0, bool aX1,
    const float* __restrict__ WY,
    const float* __restrict__ xY0, const float* __restrict__ xY1,
    float* oY0, float* oY1, bool aY0, bool aY1,
    int tid, int rank, float* part0, float* part1) {
    __syncthreads();
    int w = tid >> 5, l = tid & 31;
    if (l < 16) {
        int col = rank * 16 + l;
        const float* s0 = xX0 + w * 32;
        const float* s1 = xX1 + w * 32;
        const float4* W4 = (const float4*)WX + (size_t)(w * 32) * 64 + col;
        float4 a = make_float4(0.f, 0.f, 0.f, 0.f), b = a;
#pragma unroll 4
        for (int k = 0; k < 32; k++) {
            float4 m = __ldg(W4 + k * 64);
            fma4(a, s0[k], m); fma4(b, s1[k], m);
        }
        ((float4*)part0)[w * 32 + l] = a;
        ((float4*)part1)[w * 32 + l] = b;
    } else {
        int col = rank * 16 + (l - 16);
        const float* s0 = xY0 + w * 32;
        const float* s1 = xY1 + w * 32;
        const float4* W4 = (const float4*)WY + (size_t)(w * 32) * 64 + col;
        float4 a = make_float4(0.f, 0.f, 0.f, 0.f), b = a;
#pragma unroll 4
        for (int k = 0; k < 32; k++) {
            float4 m = __ldg(W4 + k * 64);
            fma4(a, s0[k], m); fma4(b, s1[k], m);
        }
        ((float4*)part0)[w * 32 + l] = a;
        ((float4*)part1)[w * 32 + l] = b;
    }
    __syncthreads();
    if (tid < 128) {
        int half = tid >> 6;   // 0 = X, 1 = Y
        int c = tid & 63;
        float s0 = 0.f, s1 = 0.f;
#pragma unroll
        for (int w2 = 0; w2 < 8; w2++) {
            s0 += part0[w2 * 128 + half * 64 + c];
            s1 += part1[w2 * 128 + half * 64 + c];
        }
        if (half == 0) {
            if (aX0) oX0[c] = s0;
            if (aX1) oX1[c] = s1;
        } else {
            if (aY0) oY0[c] = s0;
            if (aY1) oY1[c] = s1;
        }
    }
}

// ---------------- fused kernel: 64 main CTAs + 752 overlapped GEMM CTAs ---------
extern __shared__ float smem_f[];
__global__ __launch_bounds__(256) __cluster_dims__(CL, 1, 1)
void main_kernel(
    const float* __restrict__ aU, const float* __restrict__ bU,
    const float* __restrict__ sU, const float* __restrict__ rU,
    const float* __restrict__ sW, const float* __restrict__ sb,
    const float* __restrict__ rW, const float* __restrict__ rb,
    const float* __restrict__ Wc, const float* __restrict__ bc,
    const float* __restrict__ Wp, const float* __restrict__ bp,
    float* __restrict__ out, float* __restrict__ predsPtr) {
    int tid = threadIdx.x;

    if (blockIdx.x >= NMAIN) {
        // ============ overlapped GEMM tile CTA (4-stage cp.async pipeline) ============
        int tileIdx = blockIdx.x - NMAIN;
        int tb = tileIdx / NCB;
        int cb = tileIdx % NCB;
        int row0 = tb * GBM;
        int c0 = cb * GBN;
        int tlast = 4 * tb + 3; if (tlast > TT - 1) tlast = TT - 1;

        if (tid == 0) {
            while (atomicAdd(&g_tdone[tlast], 0) < NMAIN) __nanosleep(256);
        }
        __syncthreads();

        float* As = smem_f;                    // [4][GBK][GBM] 32KB
        float* Bs = smem_f + 4 * GBK * GBM;    // [4][GBK][GBN] 32KB
        const float* attT = &g_attT[0][0];
        unsigned sA = smem_u32(As);
        unsigned sB = smem_u32(Bs);
        int ty = tid >> 4, tx = tid & 15;

        unsigned long long accp[8][4];
#pragma unroll
        for (int i = 0; i < 8; i++)
#pragma unroll
            for (int j = 0; j < 4; j++) accp[i][j] = 0ull;

        const int NTILE = HH / GBK;   // 16

#define ISSUE_TILE(buf, kk) do {                                              \
        _Pragma("unroll")                                                     \
        for (int i_ = 0; i_ < 2; i_++) {                                      \
            int idx_ = tid * 2 + i_;                                          \
            int k_ = idx_ >> 5;                                               \
            int q_ = idx_ & 31;                                               \
            unsigned da_ = sA + (unsigned)((((buf) * GBK + k_) * GBM + q_ * 4) * 4); \
            CP16(da_, attT + (size_t)((kk) + k_) * ATP + row0 + q_ * 4);      \
            int gc_ = c0 + q_ * 4;                                            \
            if (gc_ + 3 < VV) {                                               \
                unsigned db_ = sB + (unsigned)((((buf) * GBK + k_) * GBN + q_ * 4) * 4); \
                CP16(db_, Wp + (size_t)((kk) + k_) * VV + gc_);               \
            } else {                                                          \
                *(float4*)&Bs[((buf) * GBK + k_) * GBN + q_ * 4] =            \
                    make_float4(0.f, 0.f, 0.f, 0.f);                          \
            }                                                                 \
        }                                                                     \
        CP_COMMIT();                                                          \
    } while (0)

        // prologue: fill 3 stages
        ISSUE_TILE(0, 0);
        ISSUE_TILE(1, GBK);
        ISSUE_TILE(2, 2 * GBK);
        for (int tIdx = 0; tIdx < NTILE; tIdx++) {
            int buf = tIdx & 3;
            // always issue tile tIdx+3 (clamped dummy source past the end)
            {
                int nIdx = tIdx + 3;
                int nkk = (nIdx < NTILE) ? nIdx * GBK : 0;
                ISSUE_TILE(nIdx & 3, nkk);
            }
            asm volatile("cp.async.wait_group 3;" ::: "memory");
            __syncthreads();
#pragma unroll
            for (int k = 0; k < GBK; k++) {
                float4 a01 = *((const float4*)&As[(buf * GBK + k) * GBM + ty * 8]);
                float4 a23 = *((const float4*)&As[(buf * GBK + k) * GBM + ty * 8 + 4]);
                const ulonglong2* brow = (const ulonglong2*)&Bs[(buf * GBK + k) * GBN + tx * 8];
                ulonglong2 b01 = brow[0];
                ulonglong2 b23 = brow[1];
                unsigned long long brp[4] = {b01.x, b01.y, b23.x, b23.y};
                float ar[8] = {a01.x, a01.y, a01.z, a01.w, a23.x, a23.y, a23.z, a23.w};
#pragma unroll
                for (int i = 0; i < 8; i++) {
                    unsigned long long ap = pk2(ar[i], ar[i]);
                    ffma2(accp[i][0], ap, brp[0]);
                    ffma2(accp[i][1], ap, brp[1]);
                    ffma2(accp[i][2], ap, brp[2]);
                    ffma2(accp[i][3], ap, brp[3]);
                }
            }
            __syncthreads();
        }
        asm volatile("cp.async.wait_group 0;" ::: "memory");

        float bias[8];
#pragma unroll
        for (int j = 0; j < 8; j++) {
            int gc = c0 + tx * 8 + j;
            bias[j] = (gc < VV) ? __ldg(bp + gc) : 0.f;
        }
#pragma unroll
        for (int i = 0; i < 8; i++) {
            int grow = row0 + ty * 8 + i;
            if (grow >= BB * TT) continue;
            int tt2 = grow >> 5, bb2 = grow & 31;
            int orow = bb2 * TT + tt2;
            int gc = c0 + tx * 8;
            float acc[8];
#pragma unroll
            for (int j = 0; j < 4; j++) upk2(acc[2 * j], acc[2 * j + 1], accp[i][j]);
#pragma unroll
            for (int j = 0; j < 8; j++) acc[j] += bias[j];
            if (gc + 7 < VV) {
                float4 o0 = make_float4(acc[0], acc[1], acc[2], acc[3]);
                float4 o1 = make_float4(acc[4], acc[5], acc[6], acc[7]);
                *((float4*)(out + (size_t)orow * VV + gc)) = o0;
                *((float4*)(out + (size_t)orow * VV + gc + 4)) = o1;
            } else {
#pragma unroll
                for (int j = 0; j < 8; j++)
                    if (gc + j < VV) out[(size_t)orow * VV + gc + j] = acc[j];
            }
            float rbest = -3.4e38f;
            int rbi = 0;
#pragma unroll
            for (int j = 0; j < 8; j++) {
                int gcj = gc + j;
                float v = (gcj < VV) ? acc[j] : -3.4e38f;
                if (v > rbest) { rbest = v; rbi = gcj; }
            }
#pragma unroll
            for (int o = 8; o > 0; o >>= 1) {
                float ov = __shfl_xor_sync(0xffffffffu, rbest, o);
                int oi = __shfl_xor_sync(0xffffffffu, rbi, o);
                if (ov > rbest || (ov == rbest && oi < rbi)) { rbest = ov; rbi = oi; }
            }
            if (tx == 0) {
                unsigned u = __float_as_uint(rbest);
                unsigned m = (u & 0x80000000u) ? ~u : (u | 0x80000000u);
                unsigned long long key =
                    ((unsigned long long)m << 32) | (unsigned long long)(0xFFFFFFFFu - (unsigned)rbi);
                atomicMax(&g_amax[orow], key);
            }
        }

        __shared__ int s_last;
        __syncthreads();
        if (tid == 0) {
            __threadfence();
            int old = atomicAdd(&g_gdone, 1);
            s_last = (old == NTB * NCB - 1) ? 1 : 0;
        }
        __syncthreads();
        if (s_last && predsPtr) {
            for (int r = tid; r < BB * TT; r += 256) {
                unsigned long long k2 = atomicAdd(&g_amax[r], 0ull);
                predsPtr[r] = (float)(0xFFFFFFFFu - (unsigned)(k2 & 0xFFFFFFFFull));
            }
        }
        return;
    }

    // ============ main (stack system) CTA ============
    int p = blockIdx.x >> 2;
    int rank = blockIdx.x & 3;
    int b0 = p, b1 = p + NPAIR;

    float* hs0   = smem_f;               // 8192
    float* hs1   = hs0 + 8192;
    float* bufh0 = hs1 + 8192;           // 256 each
    float* bufh1 = bufh0 + 256;
    float* ah0   = bufh1 + 256;
    float* ah1   = ah0 + 256;
    float* hred0 = ah1 + 256;
    float* hred1 = hred0 + 256;
    float* s_xw0 = hred1 + 256;          // 768 x2
    float* s_xw1 = s_xw0 + 768;
    float* s_hus0 = s_xw1 + 768;         // 768 x6 (S/B/A hu buffers)
    float* s_hus1 = s_hus0 + 768;
    float* s_hub0 = s_hus1 + 768;
    float* s_hub1 = s_hub0 + 768;
    float* s_hua0 = s_hub1 + 768;
    float* s_hua1 = s_hua0 + 768;
    float* partbig = s_hua1 + 768;       // 6144 (4 blocks of 1536)
    float* cxw0  = partbig + 6144;       // [32][192] rW@value cache, lane0
    float* cxw1  = cxw0 + SS * 192;
    float* p_s0  = cxw1 + SS * 192;      // 64 each
    float* p_s1  = p_s0 + 64;
    float* p_ah0 = p_s1 + 64;
    float* p_ah1 = p_ah0 + 64;
    float* p_b0  = p_ah1 + 64;
    float* p_b1  = p_b0 + 64;

    unsigned base_u32 = smem_u32(smem_f);
    unsigned hred_a[2], hs_a[2], bufh_a[2], ah_a[2];
    hred_a[0] = base_u32 + (unsigned)((char*)hred0 - (char*)smem_f);
    hred_a[1] = base_u32 + (unsigned)((char*)hred1 - (char*)smem_f);
    hs_a[0]   = base_u32 + (unsigned)((char*)hs0 - (char*)smem_f);
    hs_a[1]   = base_u32 + (unsigned)((char*)hs1 - (char*)smem_f);
    bufh_a[0] = base_u32 + (unsigned)((char*)bufh0 - (char*)smem_f);
    bufh_a[1] = base_u32 + (unsigned)((char*)bufh1 - (char*)smem_f);
    ah_a[0]   = base_u32 + (unsigned)((char*)ah0 - (char*)smem_f);
    ah_a[1]   = base_u32 + (unsigned)((char*)ah1 - (char*)smem_f);

    float* HS[2]   = {hs0, hs1};
    float* BUFH[2] = {bufh0, bufh1};
    float* AH[2]   = {ah0, ah1};
    float* HRED[2] = {hred0, hred1};
    float* SXW[2]  = {s_xw0, s_xw1};
    float* SHUS[2] = {s_hus0, s_hus1};
    float* SHUB[2] = {s_hub0, s_hub1};
    float* SHUA[2] = {s_hua0, s_hua1};
    float* CXW[2]  = {cxw0, cxw1};
    float* PS[2]   = {p_s0, p_s1};
    float* PAH[2]  = {p_ah0, p_ah1};
    float* PB[2]   = {p_b0, p_b1};
    int BL[2] = {b0, b1};
    float* part0 = partbig;
    float* part1 = partbig + 1536;

    {
        const float* xw = &g_tokxw[1][1][0];
        float v = sigm(xw[tid]) * tanhf(xw[2 * HH + tid]);
        bufh0[tid] = v; bufh1[tid] = v;
        if (tid < 64) { p_s0[tid] = 0.f; p_s1[tid] = 0.f; }
    }
    __syncthreads();

    int prev_stop[2] = {-1, -1};

    for (int t = 0; t < TT; t++) {
        int la_[2], np_[2], sslot_[2], stokv_[2], bpush_[2], stop_[2];
#pragma unroll
        for (int j = 0; j < 2; j++) {
            int bl = BL[j];
            la_[j]    = g_la[t][bl];
            np_[j]    = g_npop[t][bl];
            sslot_[j] = g_spush_slot[t][bl];
            stokv_[j] = g_spush_tok[t][bl];
            bpush_[j] = g_bpush_tok[t][bl];
            stop_[j]  = g_stop[t][bl];
        }
        int npmax = np_[0] > np_[1] ? np_[0] : np_[1];

        // ---- reduce chain (pop-time matvec served by push-time rW cache) ----
        for (int i = 0; i < npmax; i++) {
            bool act[2];
            int tok[2], slot[2];
#pragma unroll
            for (int j = 0; j < 2; j++) {
                act[j] = (i < np_[j]);
                tok[j] = act[j] ? (int)g_pop_tok[t][BL[j]][i] : 0;
                slot[j] = act[j] ? (int)g_pop_slot[t][BL[j]][i] : 0;
            }
            if (i > 0)
                mvq_pair(rU, HRED[0], HRED[1], SHUA[0], SHUA[1], nullptr,
                         tid, rank, part0, part1);
            __syncthreads();
            if (tid < 64) {
                int ch = rank * 64 + tid;
#pragma unroll
                for (int j = 0; j < 2; j++) {
                    if (!act[j]) continue;
                    float xwz, xwr2, xwn;
                    if (tok[j] >= 0) {
                        const float* xw = &g_tokxw[3][tok[j]][0];
                        xwz = xw[ch]; xwr2 = xw[HH + ch]; xwn = xw[2 * HH + ch];
                    } else {
                        const float* cb2 = &CXW[j][slot[j] * 192];
                        xwz = cb2[tid]; xwr2 = cb2[64 + tid]; xwn = cb2[128 + tid];
                    }
                    float hz = 0.f, hr = 0.f, hn = 0.f, hp = 0.f;
                    if (i > 0) {
                        hz = SHUA[j][ch]; hr = SHUA[j][HH + ch]; hn = SHUA[j][2 * HH + ch];
                        hp = HRED[j][ch];
                    }
                    float z = sigm(xwz + hz);
                    float r = sigm(xwr2 + hr);
                    float n = tanhf(xwn + r * hn);
                    float h = (1.f - z) * hp + z * n;
                    HRED[j][ch] = h;
                    st_peer3(hred_a[j] + (unsigned)ch * 4, rank, h);
                }
            }
            CLUSTER_SYNC();
        }

        // ---- sW+rW dual over hred (reduce-result push), rW quarter cached ----
        bool red[2] = {sslot_[0] >= 0 && stokv_[0] == -1,
                       sslot_[1] >= 0 && stokv_[1] == -1};
        if (red[0] || red[1])
            mvq2sr_pair(sW, rW, HRED[0], HRED[1], SXW[0], SXW[1],
                        &CXW[0][(red[0] ? sslot_[0] : 0) * 192],
                        &CXW[1][(red[1] ? sslot_[1] : 0) * 192],
                        red[0], red[1], sb, rb, tid, rank, partbig);

        // ---- U-streams: pair active ones (sU / bU / aU) ----
        {
            bool pu0 = sslot_[0] > 0, pu1 = sslot_[1] > 0;
            bool doS = pu0 || pu1;
            bool doB = (bpush_[0] >= 0) || (bpush_[1] >= 0);
            bool doA = (t > 0);
            const float* xS0 = pu0 ? &HS[0][(sslot_[0] - 1) * HH] : HRED[0];
            const float* xS1 = pu1 ? &HS[1][(sslot_[1] - 1) * HH] : HRED[1];
            if (doS && doB) {
                mvq2g_pair(sU, xS0, xS1, SHUS[0], SHUS[1],
                           bU, BUFH[0], BUFH[1], SHUB[0], SHUB[1],
                           tid, rank, partbig);
                if (doA)
                    mvq_pair(aU, AH[0], AH[1], SHUA[0], SHUA[1], nullptr,
                             tid, rank, part0, part1);
            } else if (doS && doA) {
                mvq2g_pair(sU, xS0, xS1, SHUS[0], SHUS[1],
                           aU, AH[0], AH[1], SHUA[0], SHUA[1],
                           tid, rank, partbig);
            } else if (doB && doA) {
                mvq2g_pair(bU, BUFH[0], BUFH[1], SHUB[0], SHUB[1],
                           aU, AH[0], AH[1], SHUA[0], SHUA[1],
                           tid, rank, partbig);
            } else if (doS) {
                mvq_pair(sU, xS0, xS1, SHUS[0], SHUS[1], nullptr, tid, rank, part0, part1);
            } else if (doB) {
                mvq_pair(bU, BUFH[0], BUFH[1], SHUB[0], SHUB[1], nullptr, tid, rank, part0, part1);
            } else if (doA) {
                mvq_pair(aU, AH[0], AH[1], SHUA[0], SHUA[1], nullptr, tid, rank, part0, part1);
            }
        }
        __syncthreads();

        // ---- all gate combines in one block ----
        if (t == 0) {
#pragma unroll
            for (int j = 0; j < 2; j++) {
                const float* xw = &g_tokxw[0][la_[j]][0];
                AH[j][tid] = sigm(xw[tid]) * tanhf(xw[2 * HH + tid]);
            }
        }
        if (tid < 64) {
            int ch = rank * 64 + tid;
#pragma unroll
            for (int j = 0; j < 2; j++) {
                if (sslot_[j] >= 0) {
                    const float* xw = (stokv_[j] >= 0) ? &g_tokxw[2][stokv_[j]][0] : SXW[j];
                    float hz = 0.f, hr = 0.f, hn = 0.f, hp = 0.f;
                    if (sslot_[j] > 0) {
                        hz = SHUS[j][ch]; hr = SHUS[j][HH + ch]; hn = SHUS[j][2 * HH + ch];
                        hp = HS[j][(sslot_[j] - 1) * HH + ch];
                    }
                    float z = sigm(xw[ch] + hz);
                    float r = sigm(xw[HH + ch] + hr);
                    float n = tanhf(xw[2 * HH + ch] + r * hn);
                    float h = (1.f - z) * hp + z * n;
                    HS[j][sslot_[j] * HH + ch] = h;
                    st_peer3(hs_a[j] + (unsigned)(sslot_[j] * HH + ch) * 4, rank, h);
                }
                if (bpush_[j] >= 0) {
                    const float* xw = &g_tokxw[1][bpush_[j]][0];
                    float z = sigm(xw[ch] + SHUB[j][ch]);
                    float r = sigm(xw[HH + ch] + SHUB[j][HH + ch]);
                    float n = tanhf(xw[2 * HH + ch] + r * SHUB[j][2 * HH + ch]);
                    float h = (1.f - z) * BUFH[j][ch] + z * n;
                    BUFH[j][ch] = h;
                    st_peer3(bufh_a[j] + (unsigned)ch * 4, rank, h);
                }
                if (t > 0) {
                    const float* xw = &g_tokxw[0][la_[j]][0];
                    float z = sigm(xw[ch] + SHUA[j][ch]);
                    float r = sigm(xw[HH + ch] + SHUA[j][HH + ch]);
                    float n = tanhf(xw[2 * HH + ch] + r * SHUA[j][2 * HH + ch]);
                    float h = (1.f - z) * AH[j][ch] + z * n;
                    AH[j][ch] = h;
                    st_peer3(ah_a[j] + (unsigned)ch * 4, rank, h);
                }
            }
        }
        CLUSTER_SYNC();

        // ---- attention pieces: pair active ones ----
        {
            bool dirty[2], acts[2], zero[2];
#pragma unroll
            for (int j = 0; j < 2; j++) {
                dirty[j] = (stop_[j] != prev_stop[j]) || (sslot_[j] >= 0);
                acts[j] = dirty[j] && stop_[j] >= 0;
                zero[j] = dirty[j] && stop_[j] < 0;
            }
            bool doP0 = acts[0] || acts[1];
            bool db[2] = {t == 0 || bpush_[0] >= 0, t == 0 || bpush_[1] >= 0};
            bool doP2 = db[0] || db[1];
            const float* xs0 = acts[0] ? &HS[0][stop_[0] * HH] : HRED[0];
            const float* xs1 = acts[1] ? &HS[1][stop_[1] * HH] : HRED[1];
            const float* W0 = Wc;
            const float* W1 = Wc + (size_t)HH * HH;
            const float* W2 = Wc + (size_t)2 * HH * HH;
            if (doP0 && doP2) {
                piece2_pair(W0, xs0, xs1, PS[0], PS[1], acts[0], acts[1],
                            W1, AH[0], AH[1], PAH[0], PAH[1], true, true,
                            tid, rank, part0, part1);
                pieceq_pair(W2, BUFH[0], BUFH[1], PB[0], PB[1], db[0], db[1],
                            tid, rank, part0, part1);
            } else if (doP0) {
                piece2_pair(W0, xs0, xs1, PS[0], PS[1], acts[0], acts[1],
                            W1, AH[0], AH[1], PAH[0], PAH[1], true, true,
                            tid, rank, part0, part1);
            } else if (doP2) {
                piece2_pair(W1, AH[0], AH[1], PAH[0], PAH[1], true, true,
                            W2, BUFH[0], BUFH[1], PB[0], PB[1], db[0], db[1],
                            tid, rank, part0, part1);
            } else {
                pieceq_pair(W1, AH[0], AH[1], PAH[0], PAH[1], true, true,
                            tid, rank, part0, part1);
            }
            __syncthreads();
            if (tid < 64) {
                if (zero[0]) PS[0][tid] = 0.f;
                if (zero[1]) PS[1][tid] = 0.f;
                int ch = rank * 64 + tid;
                float bcv = __ldg(bc + ch);
#pragma unroll
                for (int j = 0; j < 2; j++) {
                    float v = PS[j][tid] + PAH[j][tid] + PB[j][tid] + bcv;
                    g_attT[ch][t * BB + BL[j]] = tanhf(v);
                }
            }
            prev_stop[0] = stop_[0]; prev_stop[1] = stop_[1];
        }
        __syncthreads();
        if (tid == 0) { __threadfence(); atomicAdd(&g_tdone[t], 1); }
        CLUSTER_SYNC();
    }
}

// ---------------- launch ----------------
extern "C" void kernel_launch(void* const* d_in, const int* in_sizes, int n_in,
                              void* d_out, int out_size) {
    const int*   actions = (const int*)d_in[0];
    const float* embed = (const float*)d_in[1];
    const float* aW = (const float*)d_in[2];
    const float* aU = (const float*)d_in[3];
    const float* ab = (const float*)d_in[4];
    const float* bW = (const float*)d_in[5];
    const float* bU = (const float*)d_in[6];
    const float* bb = (const float*)d_in[7];
    const float* sW = (const float*)d_in[8];
    const float* sU = (const float*)d_in[9];
    const float* sb = (const float*)d_in[10];
    const float* rW = (const float*)d_in[11];
    const float* rU = (const float*)d_in[12];
    const float* rb = (const float*)d_in[13];
    const float* Wc = (const float*)d_in[14];
    const float* bc = (const float*)d_in[15];
    const float* Wp = (const float*)d_in[16];
    const float* bp = (const float*)d_in[17];

    float* outf = (float*)d_out;
    size_t nl = (size_t)BB * TT * VV;
    float* preds = nullptr;
    float* logits;
    if ((size_t)out_size >= nl + (size_t)BB * TT) {
        preds = outf;
        logits = outf + BB * TT;
    } else {
        logits = outf;
    }

    prep_kernel<<<1 + NTOK * 4, 192>>>(actions, embed, aW, ab, bW, bb, sW, sb, rW, rb);

    // smem floats: 2*8192 + 6*256 + 2*768 + 6*768 + 6144 + 2*32*192 + 6*64 = 42880 (~167.5KB)
    // gemm branch needs 4*16*128*2 = 16384 floats (64KB) <= reservation
    size_t shbytes = 42880u * sizeof(float);
    cudaFuncSetAttribute(main_kernel, cudaFuncAttributeMaxDynamicSharedMemorySize, (int)shbytes);
    int grid = NMAIN + NTB * NCB;   // 64 + 752 = 816
    main_kernel<<<grid, 256, shbytes>>>(aU, bU, sU, rU, sW, sb, rW, rb, Wc, bc,
                                        Wp, bp, logits, preds);
}

// round 15
// speedup vs baseline: 1.0012x; 1.0012x over previous
#include <cuda_runtime.h>
#include <math.h>

#define BB 32
#define SS 32
#define TT 31
#define HH 256
#define H3 768
#define VV 12000
#define NTOK 32
#define BOUND 16
#define ATP 1024
#define NPAIR 16
#define CL 4
#define NMAIN (NPAIR * CL)
#define GBM 128
#define GBN 128
#define GBK 16
#define NCB ((VV + GBN - 1) / GBN)
#define NTB 8

// ---------------- metadata ----------------
__device__ signed char g_la[TT][BB];
__device__ signed char g_npop[TT][BB];
__device__ signed char g_pop_slot[TT][BB][SS];
__device__ signed char g_pop_tok[TT][BB][SS];
__device__ signed char g_spush_slot[TT][BB];
__device__ signed char g_spush_tok[TT][BB];
__device__ signed char g_bpush_tok[TT][BB];
__device__ signed char g_stop[TT][BB];

__device__ __align__(16) float g_tokxw[4][NTOK][H3];
__device__ __align__(16) float g_attT[HH][ATP];   // row = t*BB + b
__device__ unsigned long long g_amax[BB * TT];
__device__ int g_tdone[TT];
__device__ int g_gdone;

// ---------------- asm helpers ----------------
__device__ __forceinline__ unsigned long long pk2(float lo, float hi) {
    unsigned long long r;
    asm("mov.b64 %0, {%1, %2};" : "=l"(r) : "f"(lo), "f"(hi));
    return r;
}
__device__ __forceinline__ void upk2(float& lo, float& hi, unsigned long long v) {
    asm("mov.b64 {%0, %1}, %2;" : "=f"(lo), "=f"(hi) : "l"(v));
}
__device__ __forceinline__ void ffma2(unsigned long long& d, unsigned long long a,
                                      unsigned long long b) {
    asm("fma.rn.f32x2 %0, %1, %2, %3;" : "=l"(d) : "l"(a), "l"(b), "l"(d));
}
__device__ __forceinline__ unsigned smem_u32(const void* p) {
    return (unsigned)__cvta_generic_to_shared(p);
}
__device__ __forceinline__ void st_peer(unsigned addr, unsigned peer, float v) {
    unsigned pa;
    asm volatile("mapa.shared::cluster.u32 %0, %1, %2;" : "=r"(pa) : "r"(addr), "r"(peer));
    asm volatile("st.shared::cluster.f32 [%0], %1;" :: "r"(pa), "f"(v) : "memory");
}
__device__ __forceinline__ void st_peer3(unsigned addr, int rank, float v) {
    st_peer(addr, (unsigned)((rank + 1) & 3), v);
    st_peer(addr, (unsigned)((rank + 2) & 3), v);
    st_peer(addr, (unsigned)((rank + 3) & 3), v);
}
#define CLUSTER_SYNC() do { \
    asm volatile("barrier.cluster.arrive.aligned;" ::: "memory"); \
    asm volatile("barrier.cluster.wait.aligned;" ::: "memory"); } while (0)

#define CP16(dst, src) \
    asm volatile("cp.async.cg.shared.global [%0], [%1], 16;" :: "r"(dst), "l"(src))
#define CP_COMMIT() asm volatile("cp.async.commit_group;" ::: "memory")

__device__ __forceinline__ float sigm(float v) { return 1.f / (1.f + expf(-v)); }
__device__ __forceinline__ void fma4(float4& a, float x, float4 m) {
    a.x += x * m.x; a.y += x * m.y; a.z += x * m.z; a.w += x * m.w;
}

// ---------------- prep kernel: control (block 0) + tokxw (blocks 1..128) ------
__global__ void prep_kernel(const int* __restrict__ actions,
                            const float* __restrict__ embed,
                            const float* __restrict__ aW, const float* __restrict__ ab,
                            const float* __restrict__ bW, const float* __restrict__ bb,
                            const float* __restrict__ sW, const float* __restrict__ sb,
                            const float* __restrict__ rW, const float* __restrict__ rb) {
    if (blockIdx.x == 0) {
        if (threadIdx.x >= 32) return;
        int b = threadIdx.x;
        for (int r = b; r < BB * TT; r += 32) g_amax[r] = 0ull;
        if (b < TT) g_tdone[b] = 0;
        if (b == 0) g_gdone = 0;
        int st = -1, tt_ = -1, bt = 0, acc = 1;
        signed char tm[SS];
        signed char stok[SS];

        for (int t = 0; t < TT; t++) {
            int a = actions[b * SS + t];
            int la = a * acc;
            int is_red = (la == 2) ? 1 : 0;
            int is_nt  = (la > 2 && la < BOUND) ? 1 : 0;
            int is_gen = (la >= BOUND) ? 1 : 0;

            int np = 0;
            int ir = is_red, aok = 1;
            for (int i = 0; i < SS; i++) {
                if (!(ir && aok)) break;
                int can1 = (st >= 0);
                int pslot = -1;
                if (can1) { pslot = st; st--; }
                aok = aok & can1;
                int tag = 0;
                if (ir && aok) {
                    int can2 = (tt_ >= 0);
                    if (can2) { tag = tm[tt_]; tt_--; }
                    aok = aok & can2;
                }
                int outm = ir & aok;
                if (outm) {
                    g_pop_slot[t][b][np] = (signed char)pslot;
                    g_pop_tok[t][b][np]  = stok[pslot];
                    np++;
                }
                ir = (ir - tag) * aok;
            }
            int racc = aok;
            int sslot = -1, stokv = -2;
            if (is_red && racc) {
                int can = (st + 1 < SS);
                if (can) { st++; sslot = st; stokv = -1; stok[st] = -1; }
                racc &= can;
                if (racc) {
                    int can2 = (tt_ + 1 < SS);
                    if (can2) { tt_++; tm[tt_] = 0; }
                    racc &= can2;
                }
            }
            unsigned ball = __ballot_sync(0xffffffffu, is_red);
            int tot = np;
            for (int o = 16; o > 0; o >>= 1) tot += __shfl_xor_sync(0xffffffffu, tot, o);
            int red_mult = 1;
            if (ball) red_mult = (tot == 0) ? 0 : racc;
            acc *= red_mult;

            if (is_nt) {
                int s5 = (st + 1 < SS);
                if (s5) { st++; stok[st] = (signed char)la; sslot = st; stokv = la; }
                acc *= s5;
                if (s5) {
                    int s6 = (tt_ + 1 < SS);
                    if (s6) { tt_++; tm[tt_] = 1; }
                    acc *= s6;
                }
            }
            int bpush = -1;
            if (is_gen) {
                int s7 = (st + 1 < SS);
                if (s7) { st++; stok[st] = (signed char)la; sslot = st; stokv = la; }
                acc *= s7;
                int s8 = 1;
                if (s7) {
                    s8 = (tt_ + 1 < SS);
                    if (s8) { tt_++; tm[tt_] = 0; }
                    acc *= s8;
                }
                if (s7 && s8) {
                    int s9 = (bt + 1 < SS);
                    if (s9) { bt++; bpush = la; }
                    acc *= s9;
                }
            }
            g_bpush_tok[t][b]  = (signed char)bpush;
            g_la[t][b]         = (signed char)la;
            g_npop[t][b]       = (signed char)np;
            g_spush_slot[t][b] = (signed char)sslot;
            g_spush_tok[t][b]  = (signed char)stokv;
            g_stop[t][b]       = (signed char)st;
        }
        return;
    }

    int bx = blockIdx.x - 1;   // 0..127
    int tok = bx & 31;
    int set = bx >> 5;
    const float* W  = (set == 0) ? aW : (set == 1) ? bW : (set == 2) ? sW : rW;
    const float* bi = (set == 0) ? ab : (set == 1) ? bb : (set == 2) ? sb : rb;
    int tid = threadIdx.x;  // 192 threads
    const float4* W4 = (const float4*)W;
    float4 acc = __ldg((const float4*)bi + tid);
    const float* x = embed + (size_t)tok * HH;
#pragma unroll 8
    for (int k = 0; k < HH; k++) {
        float xk = __ldg(x + k);
        float4 w = __ldg(W4 + k * 192 + tid);
        acc.x += xk * w.x; acc.y += xk * w.y; acc.z += xk * w.z; acc.w += xk * w.w;
    }
    ((float4*)(&g_tokxw[set][tok][0]))[tid] = acc;
}

// ---------------- quarter matvec for a lane pair (single matrix) ----------------
__device__ __forceinline__ void mvq_pair(const float* __restrict__ M,
                                         const float* __restrict__ x0,
                                         const float* __restrict__ x1,
                                         float* out0, float* out1,
                                         const float* __restrict__ bias,
                                         int tid, int rank,
                                         float* part0, float* part1) {
    __syncthreads();
    int w = tid >> 5, l = tid & 31;
    const float* xs0 = x0 + w * 32;
    const float* xs1 = x1 + w * 32;
    const float4* Mrow = (const float4*)M + (size_t)(w * 32) * 192;
    int col0 = (l >> 4) * 64 + rank * 16 + (l & 15);
    int col1 = 128 + rank * 16 + l;
    float4 a0 = make_float4(0.f, 0.f, 0.f, 0.f), b0 = a0, a1 = a0, b1 = a0;
#pragma unroll 4
    for (int k = 0; k < 32; k++) {
        float x0k = xs0[k], x1k = xs1[k];
        float4 m0 = __ldg(Mrow + k * 192 + col0);
        fma4(a0, x0k, m0); fma4(b0, x1k, m0);
        if (l < 16) {
            float4 m1 = __ldg(Mrow + k * 192 + col1);
            fma4(a1, x0k, m1); fma4(b1, x1k, m1);
        }
    }
    float4* p40 = (float4*)part0 + w * 48;
    float4* p41 = (float4*)part1 + w * 48;
    p40[l] = a0; p41[l] = b0;
    if (l < 16) { p40[32 + l] = a1; p41[32 + l] = b1; }
    __syncthreads();
    if (tid < 192) {
        float s0 = 0.f, s1 = 0.f;
#pragma unroll
        for (int w2 = 0; w2 < 8; w2++) { s0 += part0[w2 * 192 + tid]; s1 += part1[w2 * 192 + tid]; }
        int f4i = tid >> 2;
        int g = f4i >> 4, o = f4i & 15;
        int gc = g * 256 + rank * 64 + o * 4 + (tid & 3);
        if (bias) { float bv = __ldg(bias + gc); s0 += bv; s1 += bv; }
        out0[gc] = s0; out1[gc] = s1;
    }
}

// ---------------- generic dual matvec (two matrices, two x-streams each) --------
__device__ __forceinline__ void mvq2g_pair(
    const float* __restrict__ M1,
    const float* __restrict__ x1_0, const float* __restrict__ x1_1,
    float* o1_0, float* o1_1,
    const float* __restrict__ M2,
    const float* __restrict__ x2_0, const float* __restrict__ x2_1,
    float* o2_0, float* o2_1,
    int tid, int rank, float* part) {
    __syncthreads();
    int w = tid >> 5, l = tid & 31;
    bool lo = (l < 16);
    int col0 = (l >> 4) * 64 + rank * 16 + (l & 15);
    int col1 = 128 + rank * 16 + l;
    const float4* M1R = (const float4*)M1 + (size_t)(w * 32) * 192;
    const float4* M2R = (const float4*)M2 + (size_t)(w * 32) * 192;
    const float* a0s = x1_0 + w * 32;
    const float* a1s = x1_1 + w * 32;
    const float* b0s = x2_0 + w * 32;
    const float* b1s = x2_1 + w * 32;
    float4 z = make_float4(0.f, 0.f, 0.f, 0.f);
    float4 pA0 = z, pB0 = z, pA1 = z, pB1 = z;
    float4 qA0 = z, qB0 = z, qA1 = z, qB1 = z;
#pragma unroll 2
    for (int k = 0; k < 32; k++) {
        float xa0 = a0s[k], xa1 = a1s[k];
        float4 m1 = __ldg(M1R + k * 192 + col0);
        fma4(pA0, xa0, m1); fma4(pB0, xa1, m1);
        float xb0 = b0s[k], xb1 = b1s[k];
        float4 m2 = __ldg(M2R + k * 192 + col0);
        fma4(qA0, xb0, m2); fma4(qB0, xb1, m2);
        if (lo) {
            float4 m1b = __ldg(M1R + k * 192 + col1);
            fma4(pA1, xa0, m1b); fma4(pB1, xa1, m1b);
            float4 m2b = __ldg(M2R + k * 192 + col1);
            fma4(qA1, xb0, m2b); fma4(qB1, xb1, m2b);
        }
    }
    float4* p0 = (float4*)(part + 0 * 1536) + w * 48;
    float4* p1 = (float4*)(part + 1 * 1536) + w * 48;
    float4* p2 = (float4*)(part + 2 * 1536) + w * 48;
    float4* p3 = (float4*)(part + 3 * 1536) + w * 48;
    p0[l] = pA0; p1[l] = pB0; p2[l] = qA0; p3[l] = qB0;
    if (lo) { p0[32 + l] = pA1; p1[32 + l] = pB1; p2[32 + l] = qA1; p3[32 + l] = qB1; }
    __syncthreads();
    if (tid < 192) {
        int f4i = tid >> 2;
        int g = f4i >> 4, o = f4i & 15;
        int gc = g * 256 + rank * 64 + o * 4 + (tid & 3);
        float s0 = 0.f, s1 = 0.f, r0 = 0.f, r1 = 0.f;
#pragma unroll
        for (int w2 = 0; w2 < 8; w2++) {
            s0 += part[0 * 1536 + w2 * 192 + tid];
            s1 += part[1 * 1536 + w2 * 192 + tid];
            r0 += part[2 * 1536 + w2 * 192 + tid];
            r1 += part[3 * 1536 + w2 * 192 + tid];
        }
        o1_0[gc] = s0; o1_1[gc] = s1;
        o2_0[gc] = r0; o2_1[gc] = r1;
    }
}

// ---------------- dual matvec (sW and rW over SAME x); rW quarter cached --------
__device__ __forceinline__ void mvq2sr_pair(
    const float* __restrict__ Ms, const float* __restrict__ Mr,
    const float* __restrict__ x0, const float* __restrict__ x1,
    float* outS0, float* outS1,
    float* cR0, float* cR1, bool wr0, bool wr1,
    const float* __restrict__ sbias, const float* __restrict__ rbias,
    int tid, int rank, float* part) {
    __syncthreads();
    int w = tid >> 5, l = tid & 31;
    bool lo = (l < 16);
    int col0 = (l >> 4) * 64 + rank * 16 + (l & 15);
    int col1 = 128 + rank * 16 + l;
    const float4* MsR = (const float4*)Ms + (size_t)(w * 32) * 192;
    const float4* MrR = (const float4*)Mr + (size_t)(w * 32) * 192;
    const float* xs0 = x0 + w * 32;
    const float* xs1 = x1 + w * 32;
    float4 z = make_float4(0.f, 0.f, 0.f, 0.f);
    float4 sA0 = z, sB0 = z, sA1 = z, sB1 = z;
    float4 rA0 = z, rB0 = z, rA1 = z, rB1 = z;
#pragma unroll 2
    for (int k = 0; k < 32; k++) {
        float x0k = xs0[k], x1k = xs1[k];
        float4 ms = __ldg(MsR + k * 192 + col0);
        fma4(sA0, x0k, ms); fma4(sB0, x1k, ms);
        float4 mr = __ldg(MrR + k * 192 + col0);
        fma4(rA0, x0k, mr); fma4(rB0, x1k, mr);
        if (lo) {
            float4 ms1 = __ldg(MsR + k * 192 + col1);
            fma4(sA1, x0k, ms1); fma4(sB1, x1k, ms1);
            float4 mr1 = __ldg(MrR + k * 192 + col1);
            fma4(rA1, x0k, mr1); fma4(rB1, x1k, mr1);
        }
    }
    float4* p0 = (float4*)(part + 0 * 1536) + w * 48;
    float4* p1 = (float4*)(part + 1 * 1536) + w * 48;
    float4* p2 = (float4*)(part + 2 * 1536) + w * 48;
    float4* p3 = (float4*)(part + 3 * 1536) + w * 48;
    p0[l] = sA0; p1[l] = sB0; p2[l] = rA0; p3[l] = rB0;
    if (lo) { p0[32 + l] = sA1; p1[32 + l] = sB1; p2[32 + l] = rA1; p3[32 + l] = rB1; }
    __syncthreads();
    if (tid < 192) {
        int f4i = tid >> 2;
        int g = f4i >> 4, o = f4i & 15;
        int gc = g * 256 + rank * 64 + o * 4 + (tid & 3);
        float s0 = 0.f, s1 = 0.f, r0 = 0.f, r1 = 0.f;
#pragma unroll
        for (int w2 = 0; w2 < 8; w2++) {
            s0 += part[0 * 1536 + w2 * 192 + tid];
            s1 += part[1 * 1536 + w2 * 192 + tid];
            r0 += part[2 * 1536 + w2 * 192 + tid];
            r1 += part[3 * 1536 + w2 * 192 + tid];
        }
        float sbv = __ldg(sbias + gc), rbv = __ldg(rbias + gc);
        outS0[gc] = s0 + sbv; outS1[gc] = s1 + sbv;
        int ci = g * 64 + o * 4 + (tid & 3);
        if (wr0) cR0[ci] = r0 + rbv;
        if (wr1) cR1[ci] = r1 + rbv;
    }
}

// ---------------- single attention piece (lane pair), low lanes only ------------
__device__ __forceinline__ void pieceq_pair(const float* __restrict__ Wp,
                                            const float* __restrict__ x0,
                                            const float* __restrict__ x1,
                                            float* out0, float* out1,
                                            bool act0, bool act1,
                                            int tid, int rank,
                                            float* part0, float* part1) {
    __syncthreads();
    int w = tid >> 5, l = tid & 31;
    if (l < 16) {
        const float* xs0 = x0 + w * 32;
        const float* xs1 = x1 + w * 32;
        const float4* W4 = (const float4*)Wp + (size_t)(w * 32) * 64 + rank * 16 + l;
        float4 a = make_float4(0.f, 0.f, 0.f, 0.f), b = a;
#pragma unroll 4
        for (int k = 0; k < 32; k++) {
            float4 m = __ldg(W4 + k * 64);
            float x0k = xs0[k], x1k = xs1[k];
            fma4(a, x0k, m); fma4(b, x1k, m);
        }
        ((float4*)part0)[w * 16 + l] = a;
        ((float4*)part1)[w * 16 + l] = b;
    }
    __syncthreads();
    if (tid < 64) {
        float s0 = 0.f, s1 = 0.f;
#pragma unroll
        for (int w2 = 0; w2 < 8; w2++) { s0 += part0[w2 * 64 + tid]; s1 += part1[w2 * 64 + tid]; }
        if (act0) out0[tid] = s0;
        if (act1) out1[tid] = s1;
    }
}

// ---------------- dual attention pieces: low lanes X, high lanes Y --------------
__device__ __forceinline__ void piece2_pair(
    const float* __restrict__ WX,
    const float* __restrict__ xX0, const float* __restrict__ xX1,
    float* oX0, float* oX1, bool aX0, bool aX1,
    const float* __restrict__ WY,
    const float* __restrict__ xY0, const float* __restrict__ xY1,
    float* oY0, float* oY1, bool aY0, bool aY1,
    int tid, int rank, float* part0, float* part1) {
    __syncthreads();
    int w = tid >> 5, l = tid & 31;
    if (l < 16) {
        int col = rank * 16 + l;
        const float* s0 = xX0 + w * 32;
        const float* s1 = xX1 + w * 32;
        const float4* W4 = (const float4*)WX + (size_t)(w * 32) * 64 + col;
        float4 a = make_float4(0.f, 0.f, 0.f, 0.f), b = a;
#pragma unroll 4
        for (int k = 0; k < 32; k++) {
            float4 m = __ldg(W4 + k * 64);
            fma4(a, s0[k], m); fma4(b, s1[k], m);
        }
        ((float4*)part0)[w * 32 + l] = a;
        ((float4*)part1)[w * 32 + l] = b;
    } else {
        int col = rank * 16 + (l - 16);
        const float* s0 = xY0 + w * 32;
        const float* s1 = xY1 + w * 32;
        const float4* W4 = (const float4*)WY + (size_t)(w * 32) * 64 + col;
        float4 a = make_float4(0.f, 0.f, 0.f, 0.f), b = a;
#pragma unroll 4
        for (int k = 0; k < 32; k++) {
            float4 m = __ldg(W4 + k * 64);
            fma4(a, s0[k], m); fma4(b, s1[k], m);
        }
        ((float4*)part0)[w * 32 + l] = a;
        ((float4*)part1)[w * 32 + l] = b;
    }
    __syncthreads();
    if (tid < 128) {
        int half = tid >> 6;   // 0 = X, 1 = Y
        int c = tid & 63;
        float s0 = 0.f, s1 = 0.f;
#pragma unroll
        for (int w2 = 0; w2 < 8; w2++) {
            s0 += part0[w2 * 128 + half * 64 + c];
            s1 += part1[w2 * 128 + half * 64 + c];
        }
        if (half == 0) {
            if (aX0) oX0[c] = s0;
            if (aX1) oX1[c] = s1;
        } else {
            if (aY0) oY0[c] = s0;
            if (aY1) oY1[c] = s1;
        }
    }
}

// ---------------- fused kernel: 64 main CTAs + 752 overlapped GEMM CTAs ---------
extern __shared__ float smem_f[];
__global__ __launch_bounds__(256) __cluster_dims__(CL, 1, 1)
void main_kernel(
    const float* __restrict__ aU, const float* __restrict__ bU,
    const float* __restrict__ sU, const float* __restrict__ rU,
    const float* __restrict__ sW, const float* __restrict__ sb,
    const float* __restrict__ rW, const float* __restrict__ rb,
    const float* __restrict__ Wc, const float* __restrict__ bc,
    const float* __restrict__ Wp, const float* __restrict__ bp,
    float* __restrict__ out, float* __restrict__ predsPtr) {
    int tid = threadIdx.x;

    if (blockIdx.x >= NMAIN) {
        // ============ overlapped GEMM tile CTA (2-stage, round-13 proven) ============
        int tileIdx = blockIdx.x - NMAIN;
        int tb = tileIdx / NCB;
        int cb = tileIdx % NCB;
        int row0 = tb * GBM;
        int c0 = cb * GBN;
        int tlast = 4 * tb + 3; if (tlast > TT - 1) tlast = TT - 1;

        if (tid == 0) {
            while (atomicAdd(&g_tdone[tlast], 0) < NMAIN) __nanosleep(256);
        }
        __syncthreads();

        float* As = smem_f;
        float* Bs = smem_f + 2 * GBK * GBM;
        const float* attT = &g_attT[0][0];
        unsigned sA = smem_u32(As);
        unsigned sB = smem_u32(Bs);
        int ty = tid >> 4, tx = tid & 15;

        unsigned long long accp[8][4];
#pragma unroll
        for (int i = 0; i < 8; i++)
#pragma unroll
            for (int j = 0; j < 4; j++) accp[i][j] = 0ull;

        const int NTILE = HH / GBK;

#define ISSUE_TILE(buf, kk) do {                                              \
        _Pragma("unroll")                                                     \
        for (int i_ = 0; i_ < 2; i_++) {                                      \
            int idx_ = tid * 2 + i_;                                          \
            int k_ = idx_ >> 5;                                               \
            int q_ = idx_ & 31;                                               \
            unsigned da_ = sA + (unsigned)((((buf) * GBK + k_) * GBM + q_ * 4) * 4); \
            CP16(da_, attT + (size_t)((kk) + k_) * ATP + row0 + q_ * 4);      \
            int gc_ = c0 + q_ * 4;                                            \
            if (gc_ + 3 < VV) {                                               \
                unsigned db_ = sB + (unsigned)((((buf) * GBK + k_) * GBN + q_ * 4) * 4); \
                CP16(db_, Wp + (size_t)((kk) + k_) * VV + gc_);               \
            } else {                                                          \
                *(float4*)&Bs[((buf) * GBK + k_) * GBN + q_ * 4] =            \
                    make_float4(0.f, 0.f, 0.f, 0.f);                          \
            }                                                                 \
        }                                                                     \
        CP_COMMIT();                                                          \
    } while (0)

        ISSUE_TILE(0, 0);
        for (int tIdx = 0; tIdx < NTILE; tIdx++) {
            int buf = tIdx & 1;
            if (tIdx + 1 < NTILE) {
                ISSUE_TILE((tIdx + 1) & 1, (tIdx + 1) * GBK);
                asm volatile("cp.async.wait_group 1;" ::: "memory");
            } else {
                asm volatile("cp.async.wait_group 0;" ::: "memory");
            }
            __syncthreads();
#pragma unroll
            for (int k = 0; k < GBK; k++) {
                float4 a01 = *((const float4*)&As[(buf * GBK + k) * GBM + ty * 8]);
                float4 a23 = *((const float4*)&As[(buf * GBK + k) * GBM + ty * 8 + 4]);
                const ulonglong2* brow = (const ulonglong2*)&Bs[(buf * GBK + k) * GBN + tx * 8];
                ulonglong2 b01 = brow[0];
                ulonglong2 b23 = brow[1];
                unsigned long long brp[4] = {b01.x, b01.y, b23.x, b23.y};
                float ar[8] = {a01.x, a01.y, a01.z, a01.w, a23.x, a23.y, a23.z, a23.w};
#pragma unroll
                for (int i = 0; i < 8; i++) {
                    unsigned long long ap = pk2(ar[i], ar[i]);
                    ffma2(accp[i][0], ap, brp[0]);
                    ffma2(accp[i][1], ap, brp[1]);
                    ffma2(accp[i][2], ap, brp[2]);
                    ffma2(accp[i][3], ap, brp[3]);
                }
            }
            __syncthreads();
        }

        float bias[8];
#pragma unroll
        for (int j = 0; j < 8; j++) {
            int gc = c0 + tx * 8 + j;
            bias[j] = (gc < VV) ? __ldg(bp + gc) : 0.f;
        }
#pragma unroll
        for (int i = 0; i < 8; i++) {
            int grow = row0 + ty * 8 + i;
            if (grow >= BB * TT) continue;
            int tt2 = grow >> 5, bb2 = grow & 31;
            int orow = bb2 * TT + tt2;
            int gc = c0 + tx * 8;
            float acc[8];
#pragma unroll
            for (int j = 0; j < 4; j++) upk2(acc[2 * j], acc[2 * j + 1], accp[i][j]);
#pragma unroll
            for (int j = 0; j < 8; j++) acc[j] += bias[j];
            if (gc + 7 < VV) {
                float4 o0 = make_float4(acc[0], acc[1], acc[2], acc[3]);
                float4 o1 = make_float4(acc[4], acc[5], acc[6], acc[7]);
                *((float4*)(out + (size_t)orow * VV + gc)) = o0;
                *((float4*)(out + (size_t)orow * VV + gc + 4)) = o1;
            } else {
#pragma unroll
                for (int j = 0; j < 8; j++)
                    if (gc + j < VV) out[(size_t)orow * VV + gc + j] = acc[j];
            }
            float rbest = -3.4e38f;
            int rbi = 0;
#pragma unroll
            for (int j = 0; j < 8; j++) {
                int gcj = gc + j;
                float v = (gcj < VV) ? acc[j] : -3.4e38f;
                if (v > rbest) { rbest = v; rbi = gcj; }
            }
#pragma unroll
            for (int o = 8; o > 0; o >>= 1) {
                float ov = __shfl_xor_sync(0xffffffffu, rbest, o);
                int oi = __shfl_xor_sync(0xffffffffu, rbi, o);
                if (ov > rbest || (ov == rbest && oi < rbi)) { rbest = ov; rbi = oi; }
            }
            if (tx == 0) {
                unsigned u = __float_as_uint(rbest);
                unsigned m = (u & 0x80000000u) ? ~u : (u | 0x80000000u);
                unsigned long long key =
                    ((unsigned long long)m << 32) | (unsigned long long)(0xFFFFFFFFu - (unsigned)rbi);
                atomicMax(&g_amax[orow], key);
            }
        }

        __shared__ int s_last;
        __syncthreads();
        if (tid == 0) {
            __threadfence();
            int old = atomicAdd(&g_gdone, 1);
            s_last = (old == NTB * NCB - 1) ? 1 : 0;
        }
        __syncthreads();
        if (s_last && predsPtr) {
            for (int r = tid; r < BB * TT; r += 256) {
                unsigned long long k2 = atomicAdd(&g_amax[r], 0ull);
                predsPtr[r] = (float)(0xFFFFFFFFu - (unsigned)(k2 & 0xFFFFFFFFull));
            }
        }
        return;
    }

    // ============ main (stack system) CTA ============
    int p = blockIdx.x >> 2;
    int rank = blockIdx.x & 3;
    int b0 = p, b1 = p + NPAIR;

    float* hs0   = smem_f;               // 8192
    float* hs1   = hs0 + 8192;
    float* bufh0 = hs1 + 8192;           // 256 each
    float* bufh1 = bufh0 + 256;
    float* ah0   = bufh1 + 256;
    float* ah1   = ah0 + 256;
    float* hred0 = ah1 + 256;
    float* hred1 = hred0 + 256;
    float* s_xw0 = hred1 + 256;          // 768 x2
    float* s_xw1 = s_xw0 + 768;
    float* s_hus0 = s_xw1 + 768;         // 768 x8 (S/B/A/R hu buffers)
    float* s_hus1 = s_hus0 + 768;
    float* s_hub0 = s_hus1 + 768;
    float* s_hub1 = s_hub0 + 768;
    float* s_hua0 = s_hub1 + 768;
    float* s_hua1 = s_hua0 + 768;
    float* s_hur0 = s_hua1 + 768;
    float* s_hur1 = s_hur0 + 768;
    float* partbig = s_hur1 + 768;       // 6144 (4 blocks of 1536)
    float* cxw0  = partbig + 6144;       // [32][192] rW@value cache, lane0
    float* cxw1  = cxw0 + SS * 192;
    float* p_s0  = cxw1 + SS * 192;      // 64 each
    float* p_s1  = p_s0 + 64;
    float* p_ah0 = p_s1 + 64;
    float* p_ah1 = p_ah0 + 64;
    float* p_b0  = p_ah1 + 64;
    float* p_b1  = p_b0 + 64;

    unsigned base_u32 = smem_u32(smem_f);
    unsigned hred_a[2], hs_a[2], bufh_a[2], ah_a[2];
    hred_a[0] = base_u32 + (unsigned)((char*)hred0 - (char*)smem_f);
    hred_a[1] = base_u32 + (unsigned)((char*)hred1 - (char*)smem_f);
    hs_a[0]   = base_u32 + (unsigned)((char*)hs0 - (char*)smem_f);
    hs_a[1]   = base_u32 + (unsigned)((char*)hs1 - (char*)smem_f);
    bufh_a[0] = base_u32 + (unsigned)((char*)bufh0 - (char*)smem_f);
    bufh_a[1] = base_u32 + (unsigned)((char*)bufh1 - (char*)smem_f);
    ah_a[0]   = base_u32 + (unsigned)((char*)ah0 - (char*)smem_f);
    ah_a[1]   = base_u32 + (unsigned)((char*)ah1 - (char*)smem_f);

    float* HS[2]   = {hs0, hs1};
    float* BUFH[2] = {bufh0, bufh1};
    float* AH[2]   = {ah0, ah1};
    float* HRED[2] = {hred0, hred1};
    float* SXW[2]  = {s_xw0, s_xw1};
    float* SHUS[2] = {s_hus0, s_hus1};
    float* SHUB[2] = {s_hub0, s_hub1};
    float* SHUA[2] = {s_hua0, s_hua1};
    float* SHUR[2] = {s_hur0, s_hur1};
    float* CXW[2]  = {cxw0, cxw1};
    float* PS[2]   = {p_s0, p_s1};
    float* PAH[2]  = {p_ah0, p_ah1};
    float* PB[2]   = {p_b0, p_b1};
    int BL[2] = {b0, b1};
    float* part0 = partbig;
    float* part1 = partbig + 1536;

    {
        const float* xw = &g_tokxw[1][1][0];
        float v = sigm(xw[tid]) * tanhf(xw[2 * HH + tid]);
        bufh0[tid] = v; bufh1[tid] = v;
        if (tid < 64) { p_s0[tid] = 0.f; p_s1[tid] = 0.f; }
    }
    __syncthreads();

    int prev_stop[2] = {-1, -1};

    for (int t = 0; t < TT; t++) {
        int la_[2], np_[2], sslot_[2], stokv_[2], bpush_[2], stop_[2];
#pragma unroll
        for (int j = 0; j < 2; j++) {
            int bl = BL[j];
            la_[j]    = g_la[t][bl];
            np_[j]    = g_npop[t][bl];
            sslot_[j] = g_spush_slot[t][bl];
            stokv_[j] = g_spush_tok[t][bl];
            bpush_[j] = g_bpush_tok[t][bl];
            stop_[j]  = g_stop[t][bl];
        }
        int npmax = np_[0] > np_[1] ? np_[0] : np_[1];

        // pending U-streams (inputs are previous-step states, chain-independent)
        bool pu0 = sslot_[0] > 0, pu1 = sslot_[1] > 0;
        bool pendS = pu0 || pu1;
        bool pendB = (bpush_[0] >= 0) || (bpush_[1] >= 0);
        bool pendA = (t > 0);
        const float* xS0 = pu0 ? &HS[0][(sslot_[0] - 1) * HH] : HRED[0];
        const float* xS1 = pu1 ? &HS[1][(sslot_[1] - 1) * HH] : HRED[1];

        // ---- reduce chain: rU matvecs paired with pending U-streams ----
        for (int i = 0; i < npmax; i++) {
            bool act[2];
            int tok[2], slot[2];
#pragma unroll
            for (int j = 0; j < 2; j++) {
                act[j] = (i < np_[j]);
                tok[j] = act[j] ? (int)g_pop_tok[t][BL[j]][i] : 0;
                slot[j] = act[j] ? (int)g_pop_slot[t][BL[j]][i] : 0;
            }
            if (i > 0) {
                if (pendA) {
                    mvq2g_pair(rU, HRED[0], HRED[1], SHUR[0], SHUR[1],
                               aU, AH[0], AH[1], SHUA[0], SHUA[1],
                               tid, rank, partbig);
                    pendA = false;
                } else if (pendB) {
                    mvq2g_pair(rU, HRED[0], HRED[1], SHUR[0], SHUR[1],
                               bU, BUFH[0], BUFH[1], SHUB[0], SHUB[1],
                               tid, rank, partbig);
                    pendB = false;
                } else if (pendS) {
                    mvq2g_pair(rU, HRED[0], HRED[1], SHUR[0], SHUR[1],
                               sU, xS0, xS1, SHUS[0], SHUS[1],
                               tid, rank, partbig);
                    pendS = false;
                } else {
                    mvq_pair(rU, HRED[0], HRED[1], SHUR[0], SHUR[1], nullptr,
                             tid, rank, part0, part1);
                }
            }
            __syncthreads();
            if (tid < 64) {
                int ch = rank * 64 + tid;
#pragma unroll
                for (int j = 0; j < 2; j++) {
                    if (!act[j]) continue;
                    float xwz, xwr2, xwn;
                    if (tok[j] >= 0) {
                        const float* xw = &g_tokxw[3][tok[j]][0];
                        xwz = xw[ch]; xwr2 = xw[HH + ch]; xwn = xw[2 * HH + ch];
                    } else {
                        const float* cb2 = &CXW[j][slot[j] * 192];
                        xwz = cb2[tid]; xwr2 = cb2[64 + tid]; xwn = cb2[128 + tid];
                    }
                    float hz = 0.f, hr = 0.f, hn = 0.f, hp = 0.f;
                    if (i > 0) {
                        hz = SHUR[j][ch]; hr = SHUR[j][HH + ch]; hn = SHUR[j][2 * HH + ch];
                        hp = HRED[j][ch];
                    }
                    float z = sigm(xwz + hz);
                    float r = sigm(xwr2 + hr);
                    float n = tanhf(xwn + r * hn);
                    float h = (1.f - z) * hp + z * n;
                    HRED[j][ch] = h;
                    st_peer3(hred_a[j] + (unsigned)ch * 4, rank, h);
                }
            }
            CLUSTER_SYNC();
        }

        // ---- sW+rW dual over hred (reduce-result push), rW quarter cached ----
        bool red[2] = {sslot_[0] >= 0 && stokv_[0] == -1,
                       sslot_[1] >= 0 && stokv_[1] == -1};
        if (red[0] || red[1])
            mvq2sr_pair(sW, rW, HRED[0], HRED[1], SXW[0], SXW[1],
                        &CXW[0][(red[0] ? sslot_[0] : 0) * 192],
                        &CXW[1][(red[1] ? sslot_[1] : 0) * 192],
                        red[0], red[1], sb, rb, tid, rank, partbig);

        // ---- remaining U-streams ----
        {
            if (pendS && pendB) {
                mvq2g_pair(sU, xS0, xS1, SHUS[0], SHUS[1],
                           bU, BUFH[0], BUFH[1], SHUB[0], SHUB[1],
                           tid, rank, partbig);
                if (pendA)
                    mvq_pair(aU, AH[0], AH[1], SHUA[0], SHUA[1], nullptr,
                             tid, rank, part0, part1);
            } else if (pendS && pendA) {
                mvq2g_pair(sU, xS0, xS1, SHUS[0], SHUS[1],
                           aU, AH[0], AH[1], SHUA[0], SHUA[1],
                           tid, rank, partbig);
            } else if (pendB && pendA) {
                mvq2g_pair(bU, BUFH[0], BUFH[1], SHUB[0], SHUB[1],
                           aU, AH[0], AH[1], SHUA[0], SHUA[1],
                           tid, rank, partbig);
            } else if (pendS) {
                mvq_pair(sU, xS0, xS1, SHUS[0], SHUS[1], nullptr, tid, rank, part0, part1);
            } else if (pendB) {
                mvq_pair(bU, BUFH[0], BUFH[1], SHUB[0], SHUB[1], nullptr, tid, rank, part0, part1);
            } else if (pendA) {
                mvq_pair(aU, AH[0], AH[1], SHUA[0], SHUA[1], nullptr, tid, rank, part0, part1);
            }
        }
        __syncthreads();

        // ---- all gate combines in one block ----
        if (t == 0) {
#pragma unroll
            for (int j = 0; j < 2; j++) {
                const float* xw = &g_tokxw[0][la_[j]][0];
                AH[j][tid] = sigm(xw[tid]) * tanhf(xw[2 * HH + tid]);
            }
        }
        if (tid < 64) {
            int ch = rank * 64 + tid;
#pragma unroll
            for (int j = 0; j < 2; j++) {
                if (sslot_[j] >= 0) {
                    const float* xw = (stokv_[j] >= 0) ? &g_tokxw[2][stokv_[j]][0] : SXW[j];
                    float hz = 0.f, hr = 0.f, hn = 0.f, hp = 0.f;
                    if (sslot_[j] > 0) {
                        hz = SHUS[j][ch]; hr = SHUS[j][HH + ch]; hn = SHUS[j][2 * HH + ch];
                        hp = HS[j][(sslot_[j] - 1) * HH + ch];
                    }
                    float z = sigm(xw[ch] + hz);
                    float r = sigm(xw[HH + ch] + hr);
                    float n = tanhf(xw[2 * HH + ch] + r * hn);
                    float h = (1.f - z) * hp + z * n;
                    HS[j][sslot_[j] * HH + ch] = h;
                    st_peer3(hs_a[j] + (unsigned)(sslot_[j] * HH + ch) * 4, rank, h);
                }
                if (bpush_[j] >= 0) {
                    const float* xw = &g_tokxw[1][bpush_[j]][0];
                    float z = sigm(xw[ch] + SHUB[j][ch]);
                    float r = sigm(xw[HH + ch] + SHUB[j][HH + ch]);
                    float n = tanhf(xw[2 * HH + ch] + r * SHUB[j][2 * HH + ch]);
                    float h = (1.f - z) * BUFH[j][ch] + z * n;
                    BUFH[j][ch] = h;
                    st_peer3(bufh_a[j] + (unsigned)ch * 4, rank, h);
                }
                if (t > 0) {
                    const float* xw = &g_tokxw[0][la_[j]][0];
                    float z = sigm(xw[ch] + SHUA[j][ch]);
                    float r = sigm(xw[HH + ch] + SHUA[j][HH + ch]);
                    float n = tanhf(xw[2 * HH + ch] + r * SHUA[j][2 * HH + ch]);
                    float h = (1.f - z) * AH[j][ch] + z * n;
                    AH[j][ch] = h;
                    st_peer3(ah_a[j] + (unsigned)ch * 4, rank, h);
                }
            }
        }
        CLUSTER_SYNC();

        // ---- attention pieces: pair active ones ----
        {
            bool dirty[2], acts[2], zero[2];
#pragma unroll
            for (int j = 0; j < 2; j++) {
                dirty[j] = (stop_[j] != prev_stop[j]) || (sslot_[j] >= 0);
                acts[j] = dirty[j] && stop_[j] >= 0;
                zero[j] = dirty[j] && stop_[j] < 0;
            }
            bool doP0 = acts[0] || acts[1];
            bool db[2] = {t == 0 || bpush_[0] >= 0, t == 0 || bpush_[1] >= 0};
            bool doP2 = db[0] || db[1];
            const float* xs0 = acts[0] ? &HS[0][stop_[0] * HH] : HRED[0];
            const float* xs1 = acts[1] ? &HS[1][stop_[1] * HH] : HRED[1];
            const float* W0 = Wc;
            const float* W1 = Wc + (size_t)HH * HH;
            const float* W2 = Wc + (size_t)2 * HH * HH;
            if (doP0 && doP2) {
                piece2_pair(W0, xs0, xs1, PS[0], PS[1], acts[0], acts[1],
                            W1, AH[0], AH[1], PAH[0], PAH[1], true, true,
                            tid, rank, part0, part1);
                pieceq_pair(W2, BUFH[0], BUFH[1], PB[0], PB[1], db[0], db[1],
                            tid, rank, part0, part1);
            } else if (doP0) {
                piece2_pair(W0, xs0, xs1, PS[0], PS[1], acts[0], acts[1],
                            W1, AH[0], AH[1], PAH[0], PAH[1], true, true,
                            tid, rank, part0, part1);
            } else if (doP2) {
                piece2_pair(W1, AH[0], AH[1], PAH[0], PAH[1], true, true,
                            W2, BUFH[0], BUFH[1], PB[0], PB[1], db[0], db[1],
                            tid, rank, part0, part1);
            } else {
                pieceq_pair(W1, AH[0], AH[1], PAH[0], PAH[1], true, true,
                            tid, rank, part0, part1);
            }
            __syncthreads();
            if (tid < 64) {
                if (zero[0]) PS[0][tid] = 0.f;
                if (zero[1]) PS[1][tid] = 0.f;
                int ch = rank * 64 + tid;
                float bcv = __ldg(bc + ch);
#pragma unroll
                for (int j = 0; j < 2; j++) {
                    float v = PS[j][tid] + PAH[j][tid] + PB[j][tid] + bcv;
                    g_attT[ch][t * BB + BL[j]] = tanhf(v);
                }
            }
            prev_stop[0] = stop_[0]; prev_stop[1] = stop_[1];
        }
        __syncthreads();
        if (tid == 0) { __threadfence(); atomicAdd(&g_tdone[t], 1); }
        CLUSTER_SYNC();
    }
}

// ---------------- launch ----------------
extern "C" void kernel_launch(void* const* d_in, const int* in_sizes, int n_in,
                              void* d_out, int out_size) {
    const int*   actions = (const int*)d_in[0];
    const float* embed = (const float*)d_in[1];
    const float* aW = (const float*)d_in[2];
    const float* aU = (const float*)d_in[3];
    const float* ab = (const float*)d_in[4];
    const float* bW = (const float*)d_in[5];
    const float* bU = (const float*)d_in[6];
    const float* bb = (const float*)d_in[7];
    const float* sW = (const float*)d_in[8];
    const float* sU = (const float*)d_in[9];
    const float* sb = (const float*)d_in[10];
    const float* rW = (const float*)d_in[11];
    const float* rU = (const float*)d_in[12];
    const float* rb = (const float*)d_in[13];
    const float* Wc = (const float*)d_in[14];
    const float* bc = (const float*)d_in[15];
    const float* Wp = (const float*)d_in[16];
    const float* bp = (const float*)d_in[17];

    float* outf = (float*)d_out;
    size_t nl = (size_t)BB * TT * VV;
    float* preds = nullptr;
    float* logits;
    if ((size_t)out_size >= nl + (size_t)BB * TT) {
        preds = outf;
        logits = outf + BB * TT;
    } else {
        logits = outf;
    }

    prep_kernel<<<1 + NTOK * 4, 192>>>(actions, embed, aW, ab, bW, bb, sW, sb, rW, rb);

    // smem floats: 2*8192 + 6*256 + 2*768 + 8*768 + 6144 + 2*32*192 + 6*64 = 44416 (~173.5KB)
    size_t shbytes = 44416u * sizeof(float);
    cudaFuncSetAttribute(main_kernel, cudaFuncAttributeMaxDynamicSharedMemorySize, (int)shbytes);
    int grid = NMAIN + NTB * NCB;   // 64 + 752 = 816
    main_kernel<<<grid, 256, shbytes>>>(aU, bU, sU, rU, sW, sb, rW, rb, Wc, bc,
                                        Wp, bp, logits, preds);
}

// round 16
// speedup vs baseline: 1.0591x; 1.0578x over previous
#include <cuda_runtime.h>
#include <math.h>

#define BB 32
#define SS 32
#define TT 31
#define HH 256
#define H3 768
#define VV 12000
#define NTOK 32
#define BOUND 16
#define ATP 1024
#define NPAIR 16
#define CL 4
#define NMAIN (NPAIR * CL)
#define GBM 128
#define GBN 128
#define GBK 16
#define NCB ((VV + GBN - 1) / GBN)
#define NTB 8
#define NTH 512
#define NW 16          // warps per CTA
#define PBLK 3072      // partial block: NW*192

// ---------------- metadata ----------------
__device__ signed char g_la[TT][BB];
__device__ signed char g_npop[TT][BB];
__device__ signed char g_pop_slot[TT][BB][SS];
__device__ signed char g_pop_tok[TT][BB][SS];
__device__ signed char g_spush_slot[TT][BB];
__device__ signed char g_spush_tok[TT][BB];
__device__ signed char g_bpush_tok[TT][BB];
__device__ signed char g_stop[TT][BB];

__device__ __align__(16) float g_tokxw[4][NTOK][H3];
__device__ __align__(16) float g_attT[HH][ATP];   // row = t*BB + b
__device__ unsigned long long g_amax[BB * TT];
__device__ int g_tdone[TT];
__device__ int g_gdone;

// ---------------- asm helpers ----------------
__device__ __forceinline__ unsigned long long pk2(float lo, float hi) {
    unsigned long long r;
    asm("mov.b64 %0, {%1, %2};" : "=l"(r) : "f"(lo), "f"(hi));
    return r;
}
__device__ __forceinline__ void upk2(float& lo, float& hi, unsigned long long v) {
    asm("mov.b64 {%0, %1}, %2;" : "=f"(lo), "=f"(hi) : "l"(v));
}
__device__ __forceinline__ void ffma2(unsigned long long& d, unsigned long long a,
                                      unsigned long long b) {
    asm("fma.rn.f32x2 %0, %1, %2, %3;" : "=l"(d) : "l"(a), "l"(b), "l"(d));
}
__device__ __forceinline__ unsigned smem_u32(const void* p) {
    return (unsigned)__cvta_generic_to_shared(p);
}
__device__ __forceinline__ void st_peer(unsigned addr, unsigned peer, float v) {
    unsigned pa;
    asm volatile("mapa.shared::cluster.u32 %0, %1, %2;" : "=r"(pa) : "r"(addr), "r"(peer));
    asm volatile("st.shared::cluster.f32 [%0], %1;" :: "r"(pa), "f"(v) : "memory");
}
__device__ __forceinline__ void st_peer3(unsigned addr, int rank, float v) {
    st_peer(addr, (unsigned)((rank + 1) & 3), v);
    st_peer(addr, (unsigned)((rank + 2) & 3), v);
    st_peer(addr, (unsigned)((rank + 3) & 3), v);
}
#define CLUSTER_SYNC() do { \
    asm volatile("barrier.cluster.arrive.aligned;" ::: "memory"); \
    asm volatile("barrier.cluster.wait.aligned;" ::: "memory"); } while (0)

#define CP16(dst, src) \
    asm volatile("cp.async.cg.shared.global [%0], [%1], 16;" :: "r"(dst), "l"(src))
#define CP_COMMIT() asm volatile("cp.async.commit_group;" ::: "memory")

__device__ __forceinline__ float sigm(float v) { return 1.f / (1.f + expf(-v)); }
__device__ __forceinline__ void fma4(float4& a, float x, float4 m) {
    a.x += x * m.x; a.y += x * m.y; a.z += x * m.z; a.w += x * m.w;
}

// ---------------- prep kernel: control (block 0) + tokxw (blocks 1..128) ------
__global__ void prep_kernel(const int* __restrict__ actions,
                            const float* __restrict__ embed,
                            const float* __restrict__ aW, const float* __restrict__ ab,
                            const float* __restrict__ bW, const float* __restrict__ bb,
                            const float* __restrict__ sW, const float* __restrict__ sb,
                            const float* __restrict__ rW, const float* __restrict__ rb) {
    if (blockIdx.x == 0) {
        if (threadIdx.x >= 32) return;
        int b = threadIdx.x;
        for (int r = b; r < BB * TT; r += 32) g_amax[r] = 0ull;
        if (b < TT) g_tdone[b] = 0;
        if (b == 0) g_gdone = 0;
        int st = -1, tt_ = -1, bt = 0, acc = 1;
        signed char tm[SS];
        signed char stok[SS];

        for (int t = 0; t < TT; t++) {
            int a = actions[b * SS + t];
            int la = a * acc;
            int is_red = (la == 2) ? 1 : 0;
            int is_nt  = (la > 2 && la < BOUND) ? 1 : 0;
            int is_gen = (la >= BOUND) ? 1 : 0;

            int np = 0;
            int ir = is_red, aok = 1;
            for (int i = 0; i < SS; i++) {
                if (!(ir && aok)) break;
                int can1 = (st >= 0);
                int pslot = -1;
                if (can1) { pslot = st; st--; }
                aok = aok & can1;
                int tag = 0;
                if (ir && aok) {
                    int can2 = (tt_ >= 0);
                    if (can2) { tag = tm[tt_]; tt_--; }
                    aok = aok & can2;
                }
                int outm = ir & aok;
                if (outm) {
                    g_pop_slot[t][b][np] = (signed char)pslot;
                    g_pop_tok[t][b][np]  = stok[pslot];
                    np++;
                }
                ir = (ir - tag) * aok;
            }
            int racc = aok;
            int sslot = -1, stokv = -2;
            if (is_red && racc) {
                int can = (st + 1 < SS);
                if (can) { st++; sslot = st; stokv = -1; stok[st] = -1; }
                racc &= can;
                if (racc) {
                    int can2 = (tt_ + 1 < SS);
                    if (can2) { tt_++; tm[tt_] = 0; }
                    racc &= can2;
                }
            }
            unsigned ball = __ballot_sync(0xffffffffu, is_red);
            int tot = np;
            for (int o = 16; o > 0; o >>= 1) tot += __shfl_xor_sync(0xffffffffu, tot, o);
            int red_mult = 1;
            if (ball) red_mult = (tot == 0) ? 0 : racc;
            acc *= red_mult;

            if (is_nt) {
                int s5 = (st + 1 < SS);
                if (s5) { st++; stok[st] = (signed char)la; sslot = st; stokv = la; }
                acc *= s5;
                if (s5) {
                    int s6 = (tt_ + 1 < SS);
                    if (s6) { tt_++; tm[tt_] = 1; }
                    acc *= s6;
                }
            }
            int bpush = -1;
            if (is_gen) {
                int s7 = (st + 1 < SS);
                if (s7) { st++; stok[st] = (signed char)la; sslot = st; stokv = la; }
                acc *= s7;
                int s8 = 1;
                if (s7) {
                    s8 = (tt_ + 1 < SS);
                    if (s8) { tt_++; tm[tt_] = 0; }
                    acc *= s8;
                }
                if (s7 && s8) {
                    int s9 = (bt + 1 < SS);
                    if (s9) { bt++; bpush = la; }
                    acc *= s9;
                }
            }
            g_bpush_tok[t][b]  = (signed char)bpush;
            g_la[t][b]         = (signed char)la;
            g_npop[t][b]       = (signed char)np;
            g_spush_slot[t][b] = (signed char)sslot;
            g_spush_tok[t][b]  = (signed char)stokv;
            g_stop[t][b]       = (signed char)st;
        }
        return;
    }

    int bx = blockIdx.x - 1;
    int tok = bx & 31;
    int set = bx >> 5;
    const float* W  = (set == 0) ? aW : (set == 1) ? bW : (set == 2) ? sW : rW;
    const float* bi = (set == 0) ? ab : (set == 1) ? bb : (set == 2) ? sb : rb;
    int tid = threadIdx.x;  // 192 threads
    const float4* W4 = (const float4*)W;
    float4 acc = __ldg((const float4*)bi + tid);
    const float* x = embed + (size_t)tok * HH;
#pragma unroll 8
    for (int k = 0; k < HH; k++) {
        float xk = __ldg(x + k);
        float4 w = __ldg(W4 + k * 192 + tid);
        acc.x += xk * w.x; acc.y += xk * w.y; acc.z += xk * w.z; acc.w += xk * w.w;
    }
    ((float4*)(&g_tokxw[set][tok][0]))[tid] = acc;
}

// ---------------- quarter matvec, lane pair, 16-warp k-split ----------------
__device__ __forceinline__ void mvq_pair(const float* __restrict__ M,
                                         const float* __restrict__ x0,
                                         const float* __restrict__ x1,
                                         float* out0, float* out1,
                                         const float* __restrict__ bias,
                                         int tid, int rank,
                                         float* part0, float* part1) {
    __syncthreads();
    int w = tid >> 5, l = tid & 31;
    const float* xs0 = x0 + w * 16;
    const float* xs1 = x1 + w * 16;
    const float4* Mrow = (const float4*)M + (size_t)(w * 16) * 192;
    int col0 = (l >> 4) * 64 + rank * 16 + (l & 15);
    int col1 = 128 + rank * 16 + l;
    float4 a0 = make_float4(0.f, 0.f, 0.f, 0.f), b0 = a0, a1 = a0, b1 = a0;
#pragma unroll 4
    for (int k = 0; k < 16; k++) {
        float x0k = xs0[k], x1k = xs1[k];
        float4 m0 = __ldg(Mrow + k * 192 + col0);
        fma4(a0, x0k, m0); fma4(b0, x1k, m0);
        if (l < 16) {
            float4 m1 = __ldg(Mrow + k * 192 + col1);
            fma4(a1, x0k, m1); fma4(b1, x1k, m1);
        }
    }
    float4* p40 = (float4*)part0 + w * 48;
    float4* p41 = (float4*)part1 + w * 48;
    p40[l] = a0; p41[l] = b0;
    if (l < 16) { p40[32 + l] = a1; p41[32 + l] = b1; }
    __syncthreads();
    if (tid < 192) {
        float s0 = 0.f, s1 = 0.f;
#pragma unroll
        for (int w2 = 0; w2 < NW; w2++) { s0 += part0[w2 * 192 + tid]; s1 += part1[w2 * 192 + tid]; }
        int f4i = tid >> 2;
        int g = f4i >> 4, o = f4i & 15;
        int gc = g * 256 + rank * 64 + o * 4 + (tid & 3);
        if (bias) { float bv = __ldg(bias + gc); s0 += bv; s1 += bv; }
        out0[gc] = s0; out1[gc] = s1;
    }
}

// ---------------- generic dual matvec (two matrices), 16-warp k-split -----------
__device__ __forceinline__ void mvq2g_pair(
    const float* __restrict__ M1,
    const float* __restrict__ x1_0, const float* __restrict__ x1_1,
    float* o1_0, float* o1_1,
    const float* __restrict__ M2,
    const float* __restrict__ x2_0, const float* __restrict__ x2_1,
    float* o2_0, float* o2_1,
    int tid, int rank, float* part) {
    __syncthreads();
    int w = tid >> 5, l = tid & 31;
    bool lo = (l < 16);
    int col0 = (l >> 4) * 64 + rank * 16 + (l & 15);
    int col1 = 128 + rank * 16 + l;
    const float4* M1R = (const float4*)M1 + (size_t)(w * 16) * 192;
    const float4* M2R = (const float4*)M2 + (size_t)(w * 16) * 192;
    const float* a0s = x1_0 + w * 16;
    const float* a1s = x1_1 + w * 16;
    const float* b0s = x2_0 + w * 16;
    const float* b1s = x2_1 + w * 16;
    float4 z = make_float4(0.f, 0.f, 0.f, 0.f);
    float4 pA0 = z, pB0 = z, pA1 = z, pB1 = z;
    float4 qA0 = z, qB0 = z, qA1 = z, qB1 = z;
#pragma unroll 2
    for (int k = 0; k < 16; k++) {
        float xa0 = a0s[k], xa1 = a1s[k];
        float4 m1 = __ldg(M1R + k * 192 + col0);
        fma4(pA0, xa0, m1); fma4(pB0, xa1, m1);
        float xb0 = b0s[k], xb1 = b1s[k];
        float4 m2 = __ldg(M2R + k * 192 + col0);
        fma4(qA0, xb0, m2); fma4(qB0, xb1, m2);
        if (lo) {
            float4 m1b = __ldg(M1R + k * 192 + col1);
            fma4(pA1, xa0, m1b); fma4(pB1, xa1, m1b);
            float4 m2b = __ldg(M2R + k * 192 + col1);
            fma4(qA1, xb0, m2b); fma4(qB1, xb1, m2b);
        }
    }
    float4* p0 = (float4*)(part + 0 * PBLK) + w * 48;
    float4* p1 = (float4*)(part + 1 * PBLK) + w * 48;
    float4* p2 = (float4*)(part + 2 * PBLK) + w * 48;
    float4* p3 = (float4*)(part + 3 * PBLK) + w * 48;
    p0[l] = pA0; p1[l] = pB0; p2[l] = qA0; p3[l] = qB0;
    if (lo) { p0[32 + l] = pA1; p1[32 + l] = pB1; p2[32 + l] = qA1; p3[32 + l] = qB1; }
    __syncthreads();
    if (tid < 384) {
        int half = tid >= 192;
        int c = half ? tid - 192 : tid;
        int f4i = c >> 2;
        int g = f4i >> 4, o = f4i & 15;
        int gc = g * 256 + rank * 64 + o * 4 + (c & 3);
        float s0 = 0.f, s1 = 0.f;
        const float* pa = part + (half ? 2 : 0) * PBLK;
        const float* pb = part + (half ? 3 : 1) * PBLK;
#pragma unroll
        for (int w2 = 0; w2 < NW; w2++) {
            s0 += pa[w2 * 192 + c];
            s1 += pb[w2 * 192 + c];
        }
        if (!half) { o1_0[gc] = s0; o1_1[gc] = s1; }
        else       { o2_0[gc] = s0; o2_1[gc] = s1; }
    }
}

// ---------------- dual matvec (sW and rW over SAME x); rW quarter cached --------
__device__ __forceinline__ void mvq2sr_pair(
    const float* __restrict__ Ms, const float* __restrict__ Mr,
    const float* __restrict__ x0, const float* __restrict__ x1,
    float* outS0, float* outS1,
    float* cR0, float* cR1, bool wr0, bool wr1,
    const float* __restrict__ sbias, const float* __restrict__ rbias,
    int tid, int rank, float* part) {
    __syncthreads();
    int w = tid >> 5, l = tid & 31;
    bool lo = (l < 16);
    int col0 = (l >> 4) * 64 + rank * 16 + (l & 15);
    int col1 = 128 + rank * 16 + l;
    const float4* MsR = (const float4*)Ms + (size_t)(w * 16) * 192;
    const float4* MrR = (const float4*)Mr + (size_t)(w * 16) * 192;
    const float* xs0 = x0 + w * 16;
    const float* xs1 = x1 + w * 16;
    float4 z = make_float4(0.f, 0.f, 0.f, 0.f);
    float4 sA0 = z, sB0 = z, sA1 = z, sB1 = z;
    float4 rA0 = z, rB0 = z, rA1 = z, rB1 = z;
#pragma unroll 2
    for (int k = 0; k < 16; k++) {
        float x0k = xs0[k], x1k = xs1[k];
        float4 ms = __ldg(MsR + k * 192 + col0);
        fma4(sA0, x0k, ms); fma4(sB0, x1k, ms);
        float4 mr = __ldg(MrR + k * 192 + col0);
        fma4(rA0, x0k, mr); fma4(rB0, x1k, mr);
        if (lo) {
            float4 ms1 = __ldg(MsR + k * 192 + col1);
            fma4(sA1, x0k, ms1); fma4(sB1, x1k, ms1);
            float4 mr1 = __ldg(MrR + k * 192 + col1);
            fma4(rA1, x0k, mr1); fma4(rB1, x1k, mr1);
        }
    }
    float4* p0 = (float4*)(part + 0 * PBLK) + w * 48;
    float4* p1 = (float4*)(part + 1 * PBLK) + w * 48;
    float4* p2 = (float4*)(part + 2 * PBLK) + w * 48;
    float4* p3 = (float4*)(part + 3 * PBLK) + w * 48;
    p0[l] = sA0; p1[l] = sB0; p2[l] = rA0; p3[l] = rB0;
    if (lo) { p0[32 + l] = sA1; p1[32 + l] = sB1; p2[32 + l] = rA1; p3[32 + l] = rB1; }
    __syncthreads();
    if (tid < 384) {
        int half = tid >= 192;          // 0: sW outputs, 1: rW cache
        int c = half ? tid - 192 : tid;
        int f4i = c >> 2;
        int g = f4i >> 4, o = f4i & 15;
        int gc = g * 256 + rank * 64 + o * 4 + (c & 3);
        float s0 = 0.f, s1 = 0.f;
        const float* pa = part + (half ? 2 : 0) * PBLK;
        const float* pb = part + (half ? 3 : 1) * PBLK;
#pragma unroll
        for (int w2 = 0; w2 < NW; w2++) {
            s0 += pa[w2 * 192 + c];
            s1 += pb[w2 * 192 + c];
        }
        if (!half) {
            float sbv = __ldg(sbias + gc);
            outS0[gc] = s0 + sbv; outS1[gc] = s1 + sbv;
        } else {
            float rbv = __ldg(rbias + gc);
            int ci = g * 64 + o * 4 + (c & 3);
            if (wr0) cR0[ci] = s0 + rbv;
            if (wr1) cR1[ci] = s1 + rbv;
        }
    }
}

// ---------------- single attention piece (lane pair), 16-warp k-split -----------
__device__ __forceinline__ void pieceq_pair(const float* __restrict__ Wp,
                                            const float* __restrict__ x0,
                                            const float* __restrict__ x1,
                                            float* out0, float* out1,
                                            bool act0, bool act1,
                                            int tid, int rank,
                                            float* part0, float* part1) {
    __syncthreads();
    int w = tid >> 5, l = tid & 31;
    if (l < 16) {
        const float* xs0 = x0 + w * 16;
        const float* xs1 = x1 + w * 16;
        const float4* W4 = (const float4*)Wp + (size_t)(w * 16) * 64 + rank * 16 + l;
        float4 a = make_float4(0.f, 0.f, 0.f, 0.f), b = a;
#pragma unroll 4
        for (int k = 0; k < 16; k++) {
            float4 m = __ldg(W4 + k * 64);
            float x0k = xs0[k], x1k = xs1[k];
            fma4(a, x0k, m); fma4(b, x1k, m);
        }
        ((float4*)part0)[w * 16 + l] = a;
        ((float4*)part1)[w * 16 + l] = b;
    }
    __syncthreads();
    if (tid < 64) {
        float s0 = 0.f, s1 = 0.f;
#pragma unroll
        for (int w2 = 0; w2 < NW; w2++) { s0 += part0[w2 * 64 + tid]; s1 += part1[w2 * 64 + tid]; }
        if (act0) out0[tid] = s0;
        if (act1) out1[tid] = s1;
    }
}

// ---------------- dual attention pieces: low lanes X, high lanes Y --------------
__device__ __forceinline__ void piece2_pair(
    const float* __restrict__ WX,
    const float* __restrict__ xX0, const float* __restrict__ xX1,
    float* oX0, float* oX1, bool aX0, bool aX1,
    const float* __restrict__ WY,
    const float* __restrict__ xY0, const float* __restrict__ xY1,
    float* oY0, float* oY1, bool aY0, bool aY1,
    int tid, int rank, float* part0, float* part1) {
    __syncthreads();
    int w = tid >> 5, l = tid & 31;
    if (l < 16) {
        int col = rank * 16 + l;
        const float* s0 = xX0 + w * 16;
        const float* s1 = xX1 + w * 16;
        const float4* W4 = (const float4*)WX + (size_t)(w * 16) * 64 + col;
        float4 a = make_float4(0.f, 0.f, 0.f, 0.f), b = a;
#pragma unroll 4
        for (int k = 0; k < 16; k++) {
            float4 m = __ldg(W4 + k * 64);
            fma4(a, s0[k], m); fma4(b, s1[k], m);
        }
        ((float4*)part0)[w * 32 + l] = a;
        ((float4*)part1)[w * 32 + l] = b;
    } else {
        int col = rank * 16 + (l - 16);
        const float* s0 = xY0 + w * 16;
        const float* s1 = xY1 + w * 16;
        const float4* W4 = (const float4*)WY + (size_t)(w * 16) * 64 + col;
        float4 a = make_float4(0.f, 0.f, 0.f, 0.f), b = a;
#pragma unroll 4
        for (int k = 0; k < 16; k++) {
            float4 m = __ldg(W4 + k * 64);
            fma4(a, s0[k], m); fma4(b, s1[k], m);
        }
        ((float4*)part0)[w * 32 + l] = a;
        ((float4*)part1)[w * 32 + l] = b;
    }
    __syncthreads();
    if (tid < 128) {
        int half = tid >> 6;   // 0 = X, 1 = Y
        int c = tid & 63;
        float s0 = 0.f, s1 = 0.f;
#pragma unroll
        for (int w2 = 0; w2 < NW; w2++) {
            s0 += part0[w2 * 128 + half * 64 + c];
            s1 += part1[w2 * 128 + half * 64 + c];
        }
        if (half == 0) {
            if (aX0) oX0[c] = s0;
            if (aX1) oX1[c] = s1;
        } else {
            if (aY0) oY0[c] = s0;
            if (aY1) oY1[c] = s1;
        }
    }
}

// ---------------- fused kernel: 64 main CTAs + 752 overlapped GEMM CTAs ---------
extern __shared__ float smem_f[];
__global__ __launch_bounds__(NTH) __cluster_dims__(CL, 1, 1)
void main_kernel(
    const float* __restrict__ aU, const float* __restrict__ bU,
    const float* __restrict__ sU, const float* __restrict__ rU,
    const float* __restrict__ sW, const float* __restrict__ sb,
    const float* __restrict__ rW, const float* __restrict__ rb,
    const float* __restrict__ Wc, const float* __restrict__ bc,
    const float* __restrict__ Wp, const float* __restrict__ bp,
    float* __restrict__ out, float* __restrict__ predsPtr) {
    int tid = threadIdx.x;

    if (blockIdx.x >= NMAIN) {
        // ============ overlapped GEMM tile CTA (512 threads, 2-stage) ============
        int tileIdx = blockIdx.x - NMAIN;
        int tb = tileIdx / NCB;
        int cb = tileIdx % NCB;
        int row0 = tb * GBM;
        int c0 = cb * GBN;
        int tlast = 4 * tb + 3; if (tlast > TT - 1) tlast = TT - 1;

        if (tid == 0) {
            while (atomicAdd(&g_tdone[tlast], 0) < NMAIN) __nanosleep(256);
        }
        __syncthreads();

        float* As = smem_f;
        float* Bs = smem_f + 2 * GBK * GBM;
        const float* attT = &g_attT[0][0];
        unsigned sA = smem_u32(As);
        unsigned sB = smem_u32(Bs);
        int ty = tid >> 5, tx = tid & 31;   // 16 x 32, micro-tile 8x4

        unsigned long long accp[8][2];
#pragma unroll
        for (int i = 0; i < 8; i++) { accp[i][0] = 0ull; accp[i][1] = 0ull; }

        const int NTILE = HH / GBK;

#define ISSUE_TILE(buf, kk) do {                                              \
        int k_ = tid >> 5;                                                    \
        int q_ = tid & 31;                                                    \
        unsigned da_ = sA + (unsigned)((((buf) * GBK + k_) * GBM + q_ * 4) * 4); \
        CP16(da_, attT + (size_t)((kk) + k_) * ATP + row0 + q_ * 4);          \
        int gc_ = c0 + q_ * 4;                                                \
        if (gc_ + 3 < VV) {                                                   \
            unsigned db_ = sB + (unsigned)((((buf) * GBK + k_) * GBN + q_ * 4) * 4); \
            CP16(db_, Wp + (size_t)((kk) + k_) * VV + gc_);                   \
        } else {                                                              \
            *(float4*)&Bs[((buf) * GBK + k_) * GBN + q_ * 4] =                \
                make_float4(0.f, 0.f, 0.f, 0.f);                              \
        }                                                                     \
        CP_COMMIT();                                                          \
    } while (0)

        ISSUE_TILE(0, 0);
        for (int tIdx = 0; tIdx < NTILE; tIdx++) {
            int buf = tIdx & 1;
            if (tIdx + 1 < NTILE) {
                ISSUE_TILE((tIdx + 1) & 1, (tIdx + 1) * GBK);
                asm volatile("cp.async.wait_group 1;" ::: "memory");
            } else {
                asm volatile("cp.async.wait_group 0;" ::: "memory");
            }
            __syncthreads();
#pragma unroll
            for (int k = 0; k < GBK; k++) {
                float4 a01 = *((const float4*)&As[(buf * GBK + k) * GBM + ty * 8]);
                float4 a23 = *((const float4*)&As[(buf * GBK + k) * GBM + ty * 8 + 4]);
                ulonglong2 bq = *((const ulonglong2*)&Bs[(buf * GBK + k) * GBN + tx * 4]);
                float ar[8] = {a01.x, a01.y, a01.z, a01.w, a23.x, a23.y, a23.z, a23.w};
#pragma unroll
                for (int i = 0; i < 8; i++) {
                    unsigned long long ap = pk2(ar[i], ar[i]);
                    ffma2(accp[i][0], ap, bq.x);
                    ffma2(accp[i][1], ap, bq.y);
                }
            }
            __syncthreads();
        }

        float bias4[4];
#pragma unroll
        for (int j = 0; j < 4; j++) {
            int gc = c0 + tx * 4 + j;
            bias4[j] = (gc < VV) ? __ldg(bp + gc) : 0.f;
        }
#pragma unroll
        for (int i = 0; i < 8; i++) {
            int grow = row0 + ty * 8 + i;
            if (grow >= BB * TT) continue;
            int tt2 = grow >> 5, bb2 = grow & 31;
            int orow = bb2 * TT + tt2;
            int gc = c0 + tx * 4;
            float acc[4];
            upk2(acc[0], acc[1], accp[i][0]);
            upk2(acc[2], acc[3], accp[i][1]);
#pragma unroll
            for (int j = 0; j < 4; j++) acc[j] += bias4[j];
            if (gc + 3 < VV) {
                *((float4*)(out + (size_t)orow * VV + gc)) =
                    make_float4(acc[0], acc[1], acc[2], acc[3]);
            } else {
#pragma unroll
                for (int j = 0; j < 4; j++)
                    if (gc + j < VV) out[(size_t)orow * VV + gc + j] = acc[j];
            }
            float rbest = -3.4e38f;
            int rbi = 0;
#pragma unroll
            for (int j = 0; j < 4; j++) {
                int gcj = gc + j;
                float v = (gcj < VV) ? acc[j] : -3.4e38f;
                if (v > rbest) { rbest = v; rbi = gcj; }
            }
#pragma unroll
            for (int o = 16; o > 0; o >>= 1) {
                float ov = __shfl_xor_sync(0xffffffffu, rbest, o);
                int oi = __shfl_xor_sync(0xffffffffu, rbi, o);
                if (ov > rbest || (ov == rbest && oi < rbi)) { rbest = ov; rbi = oi; }
            }
            if (tx == 0) {
                unsigned u = __float_as_uint(rbest);
                unsigned m = (u & 0x80000000u) ? ~u : (u | 0x80000000u);
                unsigned long long key =
                    ((unsigned long long)m << 32) | (unsigned long long)(0xFFFFFFFFu - (unsigned)rbi);
                atomicMax(&g_amax[orow], key);
            }
        }

        __shared__ int s_last;
        __syncthreads();
        if (tid == 0) {
            __threadfence();
            int old = atomicAdd(&g_gdone, 1);
            s_last = (old == NTB * NCB - 1) ? 1 : 0;
        }
        __syncthreads();
        if (s_last && predsPtr) {
            for (int r = tid; r < BB * TT; r += NTH) {
                unsigned long long k2 = atomicAdd(&g_amax[r], 0ull);
                predsPtr[r] = (float)(0xFFFFFFFFu - (unsigned)(k2 & 0xFFFFFFFFull));
            }
        }
        return;
    }

    // ============ main (stack system) CTA ============
    int p = blockIdx.x >> 2;
    int rank = blockIdx.x & 3;
    int b0 = p, b1 = p + NPAIR;

    float* hs0   = smem_f;               // 8192
    float* hs1   = hs0 + 8192;
    float* bufh0 = hs1 + 8192;           // 256 each
    float* bufh1 = bufh0 + 256;
    float* ah0   = bufh1 + 256;
    float* ah1   = ah0 + 256;
    float* hred0 = ah1 + 256;
    float* hred1 = hred0 + 256;
    float* s_xw0 = hred1 + 256;          // 768 x2
    float* s_xw1 = s_xw0 + 768;
    float* s_hus0 = s_xw1 + 768;         // 768 x6
    float* s_hus1 = s_hus0 + 768;
    float* s_hub0 = s_hus1 + 768;
    float* s_hub1 = s_hub0 + 768;
    float* s_hua0 = s_hub1 + 768;
    float* s_hua1 = s_hua0 + 768;
    float* partbig = s_hua1 + 768;       // 4 * PBLK = 12288
    float* cxw0  = partbig + 4 * PBLK;   // [32][192]
    float* cxw1  = cxw0 + SS * 192;
    float* p_s0  = cxw1 + SS * 192;      // 64 each
    float* p_s1  = p_s0 + 64;
    float* p_ah0 = p_s1 + 64;
    float* p_ah1 = p_ah0 + 64;
    float* p_b0  = p_ah1 + 64;
    float* p_b1  = p_b0 + 64;

    unsigned base_u32 = smem_u32(smem_f);
    unsigned hred_a[2], hs_a[2], bufh_a[2], ah_a[2];
    hred_a[0] = base_u32 + (unsigned)((char*)hred0 - (char*)smem_f);
    hred_a[1] = base_u32 + (unsigned)((char*)hred1 - (char*)smem_f);
    hs_a[0]   = base_u32 + (unsigned)((char*)hs0 - (char*)smem_f);
    hs_a[1]   = base_u32 + (unsigned)((char*)hs1 - (char*)smem_f);
    bufh_a[0] = base_u32 + (unsigned)((char*)bufh0 - (char*)smem_f);
    bufh_a[1] = base_u32 + (unsigned)((char*)bufh1 - (char*)smem_f);
    ah_a[0]   = base_u32 + (unsigned)((char*)ah0 - (char*)smem_f);
    ah_a[1]   = base_u32 + (unsigned)((char*)ah1 - (char*)smem_f);

    float* HS[2]   = {hs0, hs1};
    float* BUFH[2] = {bufh0, bufh1};
    float* AH[2]   = {ah0, ah1};
    float* HRED[2] = {hred0, hred1};
    float* SXW[2]  = {s_xw0, s_xw1};
    float* SHUS[2] = {s_hus0, s_hus1};
    float* SHUB[2] = {s_hub0, s_hub1};
    float* SHUA[2] = {s_hua0, s_hua1};
    float* CXW[2]  = {cxw0, cxw1};
    float* PS[2]   = {p_s0, p_s1};
    float* PAH[2]  = {p_ah0, p_ah1};
    float* PB[2]   = {p_b0, p_b1};
    int BL[2] = {b0, b1};
    float* part0 = partbig;
    float* part1 = partbig + PBLK;

    if (tid < 256) {
        const float* xw = &g_tokxw[1][1][0];
        float v = sigm(xw[tid]) * tanhf(xw[2 * HH + tid]);
        bufh0[tid] = v; bufh1[tid] = v;
        if (tid < 64) { p_s0[tid] = 0.f; p_s1[tid] = 0.f; }
    }
    __syncthreads();

    int prev_stop[2] = {-1, -1};

    for (int t = 0; t < TT; t++) {
        int la_[2], np_[2], sslot_[2], stokv_[2], bpush_[2], stop_[2];
#pragma unroll
        for (int j = 0; j < 2; j++) {
            int bl = BL[j];
            la_[j]    = g_la[t][bl];
            np_[j]    = g_npop[t][bl];
            sslot_[j] = g_spush_slot[t][bl];
            stokv_[j] = g_spush_tok[t][bl];
            bpush_[j] = g_bpush_tok[t][bl];
            stop_[j]  = g_stop[t][bl];
        }
        int npmax = np_[0] > np_[1] ? np_[0] : np_[1];

        // ---- reduce chain (pop-time matvec served by push-time rW cache) ----
        for (int i = 0; i < npmax; i++) {
            bool act[2];
            int tok[2], slot[2];
#pragma unroll
            for (int j = 0; j < 2; j++) {
                act[j] = (i < np_[j]);
                tok[j] = act[j] ? (int)g_pop_tok[t][BL[j]][i] : 0;
                slot[j] = act[j] ? (int)g_pop_slot[t][BL[j]][i] : 0;
            }
            if (i > 0)
                mvq_pair(rU, HRED[0], HRED[1], SHUA[0], SHUA[1], nullptr,
                         tid, rank, part0, part1);
            __syncthreads();
            if (tid < 64) {
                int ch = rank * 64 + tid;
#pragma unroll
                for (int j = 0; j < 2; j++) {
                    if (!act[j]) continue;
                    float xwz, xwr2, xwn;
                    if (tok[j] >= 0) {
                        const float* xw = &g_tokxw[3][tok[j]][0];
                        xwz = xw[ch]; xwr2 = xw[HH + ch]; xwn = xw[2 * HH + ch];
                    } else {
                        const float* cb2 = &CXW[j][slot[j] * 192];
                        xwz = cb2[tid]; xwr2 = cb2[64 + tid]; xwn = cb2[128 + tid];
                    }
                    float hz = 0.f, hr = 0.f, hn = 0.f, hp = 0.f;
                    if (i > 0) {
                        hz = SHUA[j][ch]; hr = SHUA[j][HH + ch]; hn = SHUA[j][2 * HH + ch];
                        hp = HRED[j][ch];
                    }
                    float z = sigm(xwz + hz);
                    float r = sigm(xwr2 + hr);
                    float n = tanhf(xwn + r * hn);
                    float h = (1.f - z) * hp + z * n;
                    HRED[j][ch] = h;
                    st_peer3(hred_a[j] + (unsigned)ch * 4, rank, h);
                }
            }
            CLUSTER_SYNC();
        }

        // ---- sW+rW dual over hred (reduce-result push), rW quarter cached ----
        bool red[2] = {sslot_[0] >= 0 && stokv_[0] == -1,
                       sslot_[1] >= 0 && stokv_[1] == -1};
        if (red[0] || red[1])
            mvq2sr_pair(sW, rW, HRED[0], HRED[1], SXW[0], SXW[1],
                        &CXW[0][(red[0] ? sslot_[0] : 0) * 192],
                        &CXW[1][(red[1] ? sslot_[1] : 0) * 192],
                        red[0], red[1], sb, rb, tid, rank, partbig);

        // ---- U-streams: pair active ones (sU / bU / aU) ----
        {
            bool pu0 = sslot_[0] > 0, pu1 = sslot_[1] > 0;
            bool doS = pu0 || pu1;
            bool doB = (bpush_[0] >= 0) || (bpush_[1] >= 0);
            bool doA = (t > 0);
            const float* xS0 = pu0 ? &HS[0][(sslot_[0] - 1) * HH] : HRED[0];
            const float* xS1 = pu1 ? &HS[1][(sslot_[1] - 1) * HH] : HRED[1];
            if (doS && doB) {
                mvq2g_pair(sU, xS0, xS1, SHUS[0], SHUS[1],
                           bU, BUFH[0], BUFH[1], SHUB[0], SHUB[1],
                           tid, rank, partbig);
                if (doA)
                    mvq_pair(aU, AH[0], AH[1], SHUA[0], SHUA[1], nullptr,
                             tid, rank, part0, part1);
            } else if (doS && doA) {
                mvq2g_pair(sU, xS0, xS1, SHUS[0], SHUS[1],
                           aU, AH[0], AH[1], SHUA[0], SHUA[1],
                           tid, rank, partbig);
            } else if (doB && doA) {
                mvq2g_pair(bU, BUFH[0], BUFH[1], SHUB[0], SHUB[1],
                           aU, AH[0], AH[1], SHUA[0], SHUA[1],
                           tid, rank, partbig);
            } else if (doS) {
                mvq_pair(sU, xS0, xS1, SHUS[0], SHUS[1], nullptr, tid, rank, part0, part1);
            } else if (doB) {
                mvq_pair(bU, BUFH[0], BUFH[1], SHUB[0], SHUB[1], nullptr, tid, rank, part0, part1);
            } else if (doA) {
                mvq_pair(aU, AH[0], AH[1], SHUA[0], SHUA[1], nullptr, tid, rank, part0, part1);
            }
        }
        __syncthreads();

        // ---- all gate combines in one block ----
        if (t == 0 && tid < 256) {
#pragma unroll
            for (int j = 0; j < 2; j++) {
                const float* xw = &g_tokxw[0][la_[j]][0];
                AH[j][tid] = sigm(xw[tid]) * tanhf(xw[2 * HH + tid]);
            }
        }
        if (tid < 64) {
            int ch = rank * 64 + tid;
#pragma unroll
            for (int j = 0; j < 2; j++) {
                if (sslot_[j] >= 0) {
                    const float* xw = (stokv_[j] >= 0) ? &g_tokxw[2][stokv_[j]][0] : SXW[j];
                    float hz = 0.f, hr = 0.f, hn = 0.f, hp = 0.f;
                    if (sslot_[j] > 0) {
                        hz = SHUS[j][ch]; hr = SHUS[j][HH + ch]; hn = SHUS[j][2 * HH + ch];
                        hp = HS[j][(sslot_[j] - 1) * HH + ch];
                    }
                    float z = sigm(xw[ch] + hz);
                    float r = sigm(xw[HH + ch] + hr);
                    float n = tanhf(xw[2 * HH + ch] + r * hn);
                    float h = (1.f - z) * hp + z * n;
                    HS[j][sslot_[j] * HH + ch] = h;
                    st_peer3(hs_a[j] + (unsigned)(sslot_[j] * HH + ch) * 4, rank, h);
                }
                if (bpush_[j] >= 0) {
                    const float* xw = &g_tokxw[1][bpush_[j]][0];
                    float z = sigm(xw[ch] + SHUB[j][ch]);
                    float r = sigm(xw[HH + ch] + SHUB[j][HH + ch]);
                    float n = tanhf(xw[2 * HH + ch] + r * SHUB[j][2 * HH + ch]);
                    float h = (1.f - z) * BUFH[j][ch] + z * n;
                    BUFH[j][ch] = h;
                    st_peer3(bufh_a[j] + (unsigned)ch * 4, rank, h);
                }
                if (t > 0) {
                    const float* xw = &g_tokxw[0][la_[j]][0];
                    float z = sigm(xw[ch] + SHUA[j][ch]);
                    float r = sigm(xw[HH + ch] + SHUA[j][HH + ch]);
                    float n = tanhf(xw[2 * HH + ch] + r * SHUA[j][2 * HH + ch]);
                    float h = (1.f - z) * AH[j][ch] + z * n;
                    AH[j][ch] = h;
                    st_peer3(ah_a[j] + (unsigned)ch * 4, rank, h);
                }
            }
        }
        CLUSTER_SYNC();

        // ---- attention pieces: pair active ones ----
        {
            bool dirty[2], acts[2], zero[2];
#pragma unroll
            for (int j = 0; j < 2; j++) {
                dirty[j] = (stop_[j] != prev_stop[j]) || (sslot_[j] >= 0);
                acts[j] = dirty[j] && stop_[j] >= 0;
                zero[j] = dirty[j] && stop_[j] < 0;
            }
            bool doP0 = acts[0] || acts[1];
            bool db[2] = {t == 0 || bpush_[0] >= 0, t == 0 || bpush_[1] >= 0};
            bool doP2 = db[0] || db[1];
            const float* xs0 = acts[0] ? &HS[0][stop_[0] * HH] : HRED[0];
            const float* xs1 = acts[1] ? &HS[1][stop_[1] * HH] : HRED[1];
            const float* W0 = Wc;
            const float* W1 = Wc + (size_t)HH * HH;
            const float* W2 = Wc + (size_t)2 * HH * HH;
            if (doP0 && doP2) {
                piece2_pair(W0, xs0, xs1, PS[0], PS[1], acts[0], acts[1],
                            W1, AH[0], AH[1], PAH[0], PAH[1], true, true,
                            tid, rank, part0, part1);
                pieceq_pair(W2, BUFH[0], BUFH[1], PB[0], PB[1], db[0], db[1],
                            tid, rank, part0, part1);
            } else if (doP0) {
                piece2_pair(W0, xs0, xs1, PS[0], PS[1], acts[0], acts[1],
                            W1, AH[0], AH[1], PAH[0], PAH[1], true, true,
                            tid, rank, part0, part1);
            } else if (doP2) {
                piece2_pair(W1, AH[0], AH[1], PAH[0], PAH[1], true, true,
                            W2, BUFH[0], BUFH[1], PB[0], PB[1], db[0], db[1],
                            tid, rank, part0, part1);
            } else {
                pieceq_pair(W1, AH[0], AH[1], PAH[0], PAH[1], true, true,
                            tid, rank, part0, part1);
            }
            __syncthreads();
            if (tid < 64) {
                if (zero[0]) PS[0][tid] = 0.f;
                if (zero[1]) PS[1][tid] = 0.f;
                int ch = rank * 64 + tid;
                float bcv = __ldg(bc + ch);
#pragma unroll
                for (int j = 0; j < 2; j++) {
                    float v = PS[j][tid] + PAH[j][tid] + PB[j][tid] + bcv;
                    g_attT[ch][t * BB + BL[j]] = tanhf(v);
                }
            }
            prev_stop[0] = stop_[0]; prev_stop[1] = stop_[1];
        }
        __syncthreads();
        if (tid == 0) { __threadfence(); atomicAdd(&g_tdone[t], 1); }
        CLUSTER_SYNC();
    }
}

// ---------------- launch ----------------
extern "C" void kernel_launch(void* const* d_in, const int* in_sizes, int n_in,
                              void* d_out, int out_size) {
    const int*   actions = (const int*)d_in[0];
    const float* embed = (const float*)d_in[1];
    const float* aW = (const float*)d_in[2];
    const float* aU = (const float*)d_in[3];
    const float* ab = (const float*)d_in[4];
    const float* bW = (const float*)d_in[5];
    const float* bU = (const float*)d_in[6];
    const float* bb = (const float*)d_in[7];
    const float* sW = (const float*)d_in[8];
    const float* sU = (const float*)d_in[9];
    const float* sb = (const float*)d_in[10];
    const float* rW = (const float*)d_in[11];
    const float* rU = (const float*)d_in[12];
    const float* rb = (const float*)d_in[13];
    const float* Wc = (const float*)d_in[14];
    const float* bc = (const float*)d_in[15];
    const float* Wp = (const float*)d_in[16];
    const float* bp = (const float*)d_in[17];

    float* outf = (float*)d_out;
    size_t nl = (size_t)BB * TT * VV;
    float* preds = nullptr;
    float* logits;
    if ((size_t)out_size >= nl + (size_t)BB * TT) {
        preds = outf;
        logits = outf + BB * TT;
    } else {
        logits = outf;
    }

    prep_kernel<<<1 + NTOK * 4, 192>>>(actions, embed, aW, ab, bW, bb, sW, sb, rW, rb);

    // smem floats: 2*8192 + 6*256 + 2*768 + 6*768 + 4*3072 + 2*32*192 + 6*64 = 49024 (~191.5KB)
    size_t shbytes = 49024u * sizeof(float);
    cudaFuncSetAttribute(main_kernel, cudaFuncAttributeMaxDynamicSharedMemorySize, (int)shbytes);
    int grid = NMAIN + NTB * NCB;   // 64 + 752 = 816
    main_kernel<<<grid, NTH, shbytes>>>(aU, bU, sU, rU, sW, sb, rW, rb, Wc, bc,
                                        Wp, bp, logits, preds);
}